// round 2
// baseline (speedup 1.0000x reference)
#include <cuda_runtime.h>
#include <math.h>

#define SQ 2048
#define NB 2
#define NH 16
#define DKH 64
#define DM 1024
#define NBH (NB * NH)

// ---- device scratch (alloc-free, per harness rules) ----
__device__ float g_qh[(size_t)NBH * SQ * DKH];     // 16 MB
__device__ float g_kh[(size_t)NBH * SQ * DKH];     // 16 MB
__device__ float g_vh[(size_t)NBH * SQ * DKH];     // 16 MB
__device__ float g_ctx[(size_t)NB * SQ * DM];      // 16 MB
__device__ float g_att_scratch[(size_t)NBH * SQ * SQ]; // 512 MB (only used if d_out lacks attention)

// ============================================================
// C[M,N] = X[M,K] @ W[N,K]^T + bias[N]
// MODE 0: row-major out[M,N]
// MODE 1: head scatter out[((b*NH+h)*SQ+s)*DKH+d], m=(b,s), n=(h,d)
// 128x128 tile, BK=8, 256 threads, 8x8 per thread.
// ============================================================
template <int MODE>
__global__ __launch_bounds__(256, 2)
void sgemm_xwt(const float* __restrict__ X, const float* __restrict__ W,
               const float* __restrict__ bias, float* __restrict__ out,
               int M, int N, int K)
{
    __shared__ float As[8][128];
    __shared__ float Bs[8][128];
    const int tid = threadIdx.x;
    const int tx = tid & 15;
    const int ty = tid >> 4;
    const int m0 = blockIdx.y * 128;
    const int n0 = blockIdx.x * 128;
    const int lr = tid >> 1;          // 0..127
    const int lk = (tid & 1) * 4;     // 0 or 4

    const float* Xp = X + (size_t)(m0 + lr) * K + lk;
    const float* Wp = W + (size_t)(n0 + lr) * K + lk;

    float acc[8][8];
#pragma unroll
    for (int i = 0; i < 8; i++)
#pragma unroll
        for (int j = 0; j < 8; j++) acc[i][j] = 0.0f;

    for (int k0 = 0; k0 < K; k0 += 8) {
        float4 xa = *(const float4*)(Xp + k0);
        float4 wb = *(const float4*)(Wp + k0);
        As[lk + 0][lr] = xa.x; As[lk + 1][lr] = xa.y;
        As[lk + 2][lr] = xa.z; As[lk + 3][lr] = xa.w;
        Bs[lk + 0][lr] = wb.x; Bs[lk + 1][lr] = wb.y;
        Bs[lk + 2][lr] = wb.z; Bs[lk + 3][lr] = wb.w;
        __syncthreads();
#pragma unroll
        for (int kk = 0; kk < 8; kk++) {
            float a[8], b[8];
            *(float4*)&a[0] = *(const float4*)&As[kk][ty * 8];
            *(float4*)&a[4] = *(const float4*)&As[kk][ty * 8 + 4];
            *(float4*)&b[0] = *(const float4*)&Bs[kk][tx * 8];
            *(float4*)&b[4] = *(const float4*)&Bs[kk][tx * 8 + 4];
#pragma unroll
            for (int i = 0; i < 8; i++)
#pragma unroll
                for (int j = 0; j < 8; j++)
                    acc[i][j] += a[i] * b[j];
        }
        __syncthreads();
    }

#pragma unroll
    for (int i = 0; i < 8; i++) {
        const int m = m0 + ty * 8 + i;
#pragma unroll
        for (int j = 0; j < 8; j++) {
            const int n = n0 + tx * 8 + j;
            const float vv = acc[i][j] + bias[n];
            if (MODE == 0) {
                out[(size_t)m * N + n] = vv;
            } else {
                const int bidx = m / SQ, s = m % SQ;
                const int h = n / DKH, d = n % DKH;
                out[(((size_t)(bidx * NH + h)) * SQ + s) * DKH + d] = vv;
            }
        }
    }
}

// ============================================================
// Pre-softmax scores: att[bh,q,k] = (Qh[bh,q,:] . Kh[bh,k,:]) / 8, mask applied.
// 128x128 tile, K=64, same micro-kernel.
// ============================================================
__global__ __launch_bounds__(256, 2)
void scores_kernel(const int* __restrict__ mask, float* __restrict__ att)
{
    __shared__ float As[8][128];
    __shared__ float Bs[8][128];
    const int tid = threadIdx.x;
    const int tx = tid & 15;
    const int ty = tid >> 4;
    const int bh = blockIdx.z;
    const int b  = bh / NH;
    const int q0 = blockIdx.y * 128;
    const int n0 = blockIdx.x * 128;
    const float* Q  = g_qh + (size_t)bh * SQ * DKH;
    const float* Kh = g_kh + (size_t)bh * SQ * DKH;
    const int lr = tid >> 1;
    const int lk = (tid & 1) * 4;

    float acc[8][8];
#pragma unroll
    for (int i = 0; i < 8; i++)
#pragma unroll
        for (int j = 0; j < 8; j++) acc[i][j] = 0.0f;

#pragma unroll
    for (int k0 = 0; k0 < DKH; k0 += 8) {
        float4 xa = *(const float4*)(Q  + (size_t)(q0 + lr) * DKH + k0 + lk);
        float4 wb = *(const float4*)(Kh + (size_t)(n0 + lr) * DKH + k0 + lk);
        As[lk + 0][lr] = xa.x; As[lk + 1][lr] = xa.y;
        As[lk + 2][lr] = xa.z; As[lk + 3][lr] = xa.w;
        Bs[lk + 0][lr] = wb.x; Bs[lk + 1][lr] = wb.y;
        Bs[lk + 2][lr] = wb.z; Bs[lk + 3][lr] = wb.w;
        __syncthreads();
#pragma unroll
        for (int kk = 0; kk < 8; kk++) {
            float a[8], bb[8];
            *(float4*)&a[0]  = *(const float4*)&As[kk][ty * 8];
            *(float4*)&a[4]  = *(const float4*)&As[kk][ty * 8 + 4];
            *(float4*)&bb[0] = *(const float4*)&Bs[kk][tx * 8];
            *(float4*)&bb[4] = *(const float4*)&Bs[kk][tx * 8 + 4];
#pragma unroll
            for (int i = 0; i < 8; i++)
#pragma unroll
                for (int j = 0; j < 8; j++)
                    acc[i][j] += a[i] * bb[j];
        }
        __syncthreads();
    }

#pragma unroll
    for (int i = 0; i < 8; i++) {
        const int qq = q0 + ty * 8 + i;
#pragma unroll
        for (int j = 0; j < 8; j++) {
            const int kk2 = n0 + tx * 8 + j;
            float v = acc[i][j] * 0.125f;  // 1/sqrt(64)
            if (mask[(size_t)b * SQ * SQ + (size_t)qq * SQ + kk2] == 0) v = 1e-9f;
            att[((size_t)bh * SQ + qq) * SQ + kk2] = v;
        }
    }
}

// ============================================================
// Row softmax in place. 1 block per row (2048 elems), 256 threads.
// ============================================================
__global__ __launch_bounds__(256)
void softmax_kernel(float* __restrict__ att)
{
    const size_t row = blockIdx.x;
    float* p = att + row * (size_t)SQ;
    const int tid = threadIdx.x;

    float4 v0 = ((const float4*)p)[tid];
    float4 v1 = ((const float4*)p)[tid + 256];

    float mx = fmaxf(fmaxf(fmaxf(v0.x, v0.y), fmaxf(v0.z, v0.w)),
                     fmaxf(fmaxf(v1.x, v1.y), fmaxf(v1.z, v1.w)));
    __shared__ float red[8];
    __shared__ float bcast;
#pragma unroll
    for (int o = 16; o > 0; o >>= 1) mx = fmaxf(mx, __shfl_xor_sync(0xffffffffu, mx, o));
    if ((tid & 31) == 0) red[tid >> 5] = mx;
    __syncthreads();
    if (tid == 0) {
        float m = red[0];
#pragma unroll
        for (int w = 1; w < 8; w++) m = fmaxf(m, red[w]);
        bcast = m;
    }
    __syncthreads();
    const float m = bcast;
    __syncthreads();   // protect red/bcast reuse

    v0.x = __expf(v0.x - m); v0.y = __expf(v0.y - m);
    v0.z = __expf(v0.z - m); v0.w = __expf(v0.w - m);
    v1.x = __expf(v1.x - m); v1.y = __expf(v1.y - m);
    v1.z = __expf(v1.z - m); v1.w = __expf(v1.w - m);
    float s = v0.x + v0.y + v0.z + v0.w + v1.x + v1.y + v1.z + v1.w;
#pragma unroll
    for (int o = 16; o > 0; o >>= 1) s += __shfl_xor_sync(0xffffffffu, s, o);
    if ((tid & 31) == 0) red[tid >> 5] = s;
    __syncthreads();
    if (tid == 0) {
        float t = 0.0f;
#pragma unroll
        for (int w = 0; w < 8; w++) t += red[w];
        bcast = 1.0f / t;
    }
    __syncthreads();
    const float inv = bcast;

    v0.x *= inv; v0.y *= inv; v0.z *= inv; v0.w *= inv;
    v1.x *= inv; v1.y *= inv; v1.z *= inv; v1.w *= inv;
    ((float4*)p)[tid] = v0;
    ((float4*)p)[tid + 256] = v1;
}

// ============================================================
// ctx[b,q,h*64+d] = sum_k att[bh,q,k] * Vh[bh,k,d]
// BM=128, BN=64(=DKH), BK=16, 256 threads, 8x4 per thread.
// ============================================================
__global__ __launch_bounds__(256, 2)
void pv_kernel(const float* __restrict__ att)
{
    __shared__ float As[16][128];
    __shared__ float Vs[16][64];
    const int tid = threadIdx.x;
    const int tx = tid & 15;
    const int ty = tid >> 4;
    const int bh = blockIdx.y;
    const int b = bh / NH, h = bh % NH;
    const int q0 = blockIdx.x * 128;
    const float* A = att + ((size_t)bh * SQ + q0) * SQ;
    const float* V = g_vh + (size_t)bh * SQ * DKH;

    const int lrA = tid >> 1;         // 0..127 (q row)
    const int lkA = (tid & 1) * 8;    // 0 or 8
    const int lrV = tid >> 4;         // 0..15 (k row)
    const int lcV = (tid & 15) * 4;   // 0..60

    float acc[8][4];
#pragma unroll
    for (int i = 0; i < 8; i++)
#pragma unroll
        for (int j = 0; j < 4; j++) acc[i][j] = 0.0f;

    for (int k0 = 0; k0 < SQ; k0 += 16) {
        float4 a0 = *(const float4*)(A + (size_t)lrA * SQ + k0 + lkA);
        float4 a1 = *(const float4*)(A + (size_t)lrA * SQ + k0 + lkA + 4);
        *(float4*)&Vs[lrV][lcV] = *(const float4*)(V + (size_t)(k0 + lrV) * DKH + lcV);
        As[lkA + 0][lrA] = a0.x; As[lkA + 1][lrA] = a0.y;
        As[lkA + 2][lrA] = a0.z; As[lkA + 3][lrA] = a0.w;
        As[lkA + 4][lrA] = a1.x; As[lkA + 5][lrA] = a1.y;
        As[lkA + 6][lrA] = a1.z; As[lkA + 7][lrA] = a1.w;
        __syncthreads();
#pragma unroll
        for (int kk = 0; kk < 16; kk++) {
            float a[8], bv[4];
            *(float4*)&a[0]  = *(const float4*)&As[kk][ty * 8];
            *(float4*)&a[4]  = *(const float4*)&As[kk][ty * 8 + 4];
            *(float4*)&bv[0] = *(const float4*)&Vs[kk][tx * 4];
#pragma unroll
            for (int i = 0; i < 8; i++)
#pragma unroll
                for (int j = 0; j < 4; j++)
                    acc[i][j] += a[i] * bv[j];
        }
        __syncthreads();
    }

#pragma unroll
    for (int i = 0; i < 8; i++) {
        const int q = q0 + ty * 8 + i;
#pragma unroll
        for (int j = 0; j < 4; j++) {
            const int d = tx * 4 + j;
            g_ctx[((size_t)b * SQ + q) * DM + h * DKH + d] = acc[i][j];
        }
    }
}

// ============================================================
extern "C" void kernel_launch(void* const* d_in, const int* in_sizes, int n_in,
                              void* d_out, int out_size)
{
    const float* q    = (const float*)d_in[0];
    const float* k    = (const float*)d_in[1];
    const float* v    = (const float*)d_in[2];
    const int*   mask = (const int*)  d_in[3];
    const float* Wq   = (const float*)d_in[4];
    const float* bq   = (const float*)d_in[5];
    const float* Wk   = (const float*)d_in[6];
    const float* bk   = (const float*)d_in[7];
    const float* Wv   = (const float*)d_in[8];
    const float* bv   = (const float*)d_in[9];
    const float* Wo   = (const float*)d_in[10];
    const float* bo   = (const float*)d_in[11];

    float *qh, *kh, *vh, *ctx, *attscr;
    cudaGetSymbolAddress((void**)&qh,     g_qh);
    cudaGetSymbolAddress((void**)&kh,     g_kh);
    cudaGetSymbolAddress((void**)&vh,     g_vh);
    cudaGetSymbolAddress((void**)&ctx,    g_ctx);
    cudaGetSymbolAddress((void**)&attscr, g_att_scratch);

    const long OUT_ELEMS = (long)NB * SQ * DM;            // 4,194,304
    const long ATT_ELEMS = (long)NBH * SQ * (long)SQ;     // 134,217,728
    float* outp = (float*)d_out;
    float* attp;
    if ((long)out_size >= OUT_ELEMS + ATT_ELEMS) {
        attp = outp + OUT_ELEMS;                 // (output, attention) concatenated
    } else if ((long)out_size == ATT_ELEMS) {
        attp = outp;                              // attention-only output
        outp = qh;                                // final proj result discarded (qh dead by then)
    } else {
        attp = attscr;                            // output-only: attention to scratch
    }

    const dim3 gProj(DM / 128, (NB * SQ) / 128); // (8, 32)
    sgemm_xwt<1><<<gProj, 256>>>(q, Wq, bq, qh, NB * SQ, DM, DM);
    sgemm_xwt<1><<<gProj, 256>>>(k, Wk, bk, kh, NB * SQ, DM, DM);
    sgemm_xwt<1><<<gProj, 256>>>(v, Wv, bv, vh, NB * SQ, DM, DM);

    scores_kernel<<<dim3(SQ / 128, SQ / 128, NBH), 256>>>(mask, attp); // (16,16,32)
    softmax_kernel<<<NBH * SQ, 256>>>(attp);                            // 65536 rows
    pv_kernel<<<dim3(SQ / 128, NBH), 256>>>(attp);                      // (16,32)

    sgemm_xwt<0><<<gProj, 256>>>(ctx, Wo, bo, outp, NB * SQ, DM, DM);
}

// round 3
// speedup vs baseline: 1.0018x; 1.0018x over previous
#include <cuda_runtime.h>
#include <math.h>

#define SQ 2048
#define NB 2
#define NH 16
#define DKH 64
#define DM 1024
#define NBH (NB * NH)

// ---- device scratch (alloc-free, per harness rules) ----
__device__ float g_qh[(size_t)NBH * SQ * DKH];     // 16 MB
__device__ float g_kh[(size_t)NBH * SQ * DKH];     // 16 MB
__device__ float g_vh[(size_t)NBH * SQ * DKH];     // 16 MB
__device__ float g_ctx[(size_t)NB * SQ * DM];      // 16 MB
__device__ float g_att_scratch[(size_t)NBH * SQ * SQ]; // 512 MB (only used if d_out lacks attention)

// ============================================================
// C[M,N] = X[M,K] @ W[N,K]^T + bias[N]
// MODE 0: row-major out[M,N]
// MODE 1: head scatter out[((b*NH+h)*SQ+s)*DKH+d], m=(b,s), n=(h,d)
// 128x128 tile, BK=8, 256 threads, 8x8 per thread.
// ============================================================
template <int MODE>
__global__ __launch_bounds__(256, 2)
void sgemm_xwt(const float* __restrict__ X, const float* __restrict__ W,
               const float* __restrict__ bias, float* __restrict__ out,
               int M, int N, int K)
{
    __shared__ float As[8][128];
    __shared__ float Bs[8][128];
    const int tid = threadIdx.x;
    const int tx = tid & 15;
    const int ty = tid >> 4;
    const int m0 = blockIdx.y * 128;
    const int n0 = blockIdx.x * 128;
    const int lr = tid >> 1;          // 0..127
    const int lk = (tid & 1) * 4;     // 0 or 4

    const float* Xp = X + (size_t)(m0 + lr) * K + lk;
    const float* Wp = W + (size_t)(n0 + lr) * K + lk;

    float acc[8][8];
#pragma unroll
    for (int i = 0; i < 8; i++)
#pragma unroll
        for (int j = 0; j < 8; j++) acc[i][j] = 0.0f;

    for (int k0 = 0; k0 < K; k0 += 8) {
        float4 xa = *(const float4*)(Xp + k0);
        float4 wb = *(const float4*)(Wp + k0);
        As[lk + 0][lr] = xa.x; As[lk + 1][lr] = xa.y;
        As[lk + 2][lr] = xa.z; As[lk + 3][lr] = xa.w;
        Bs[lk + 0][lr] = wb.x; Bs[lk + 1][lr] = wb.y;
        Bs[lk + 2][lr] = wb.z; Bs[lk + 3][lr] = wb.w;
        __syncthreads();
#pragma unroll
        for (int kk = 0; kk < 8; kk++) {
            float a[8], b[8];
            *(float4*)&a[0] = *(const float4*)&As[kk][ty * 8];
            *(float4*)&a[4] = *(const float4*)&As[kk][ty * 8 + 4];
            *(float4*)&b[0] = *(const float4*)&Bs[kk][tx * 8];
            *(float4*)&b[4] = *(const float4*)&Bs[kk][tx * 8 + 4];
#pragma unroll
            for (int i = 0; i < 8; i++)
#pragma unroll
                for (int j = 0; j < 8; j++)
                    acc[i][j] += a[i] * b[j];
        }
        __syncthreads();
    }

#pragma unroll
    for (int i = 0; i < 8; i++) {
        const int m = m0 + ty * 8 + i;
#pragma unroll
        for (int j = 0; j < 8; j++) {
            const int n = n0 + tx * 8 + j;
            const float vv = acc[i][j] + bias[n];
            if (MODE == 0) {
                out[(size_t)m * N + n] = vv;
            } else {
                const int bidx = m / SQ, s = m % SQ;
                const int h = n / DKH, d = n % DKH;
                out[(((size_t)(bidx * NH + h)) * SQ + s) * DKH + d] = vv;
            }
        }
    }
}

// ============================================================
// Pre-softmax scores: att[bh,q,k] = (Qh[bh,q,:] . Kh[bh,k,:]) / 8, mask applied.
// 128x128 tile, K=64, same micro-kernel.
// ============================================================
__global__ __launch_bounds__(256, 2)
void scores_kernel(const int* __restrict__ mask, float* __restrict__ att)
{
    __shared__ float As[8][128];
    __shared__ float Bs[8][128];
    const int tid = threadIdx.x;
    const int tx = tid & 15;
    const int ty = tid >> 4;
    const int bh = blockIdx.z;
    const int b  = bh / NH;
    const int q0 = blockIdx.y * 128;
    const int n0 = blockIdx.x * 128;
    const float* Q  = g_qh + (size_t)bh * SQ * DKH;
    const float* Kh = g_kh + (size_t)bh * SQ * DKH;
    const int lr = tid >> 1;
    const int lk = (tid & 1) * 4;

    float acc[8][8];
#pragma unroll
    for (int i = 0; i < 8; i++)
#pragma unroll
        for (int j = 0; j < 8; j++) acc[i][j] = 0.0f;

#pragma unroll
    for (int k0 = 0; k0 < DKH; k0 += 8) {
        float4 xa = *(const float4*)(Q  + (size_t)(q0 + lr) * DKH + k0 + lk);
        float4 wb = *(const float4*)(Kh + (size_t)(n0 + lr) * DKH + k0 + lk);
        As[lk + 0][lr] = xa.x; As[lk + 1][lr] = xa.y;
        As[lk + 2][lr] = xa.z; As[lk + 3][lr] = xa.w;
        Bs[lk + 0][lr] = wb.x; Bs[lk + 1][lr] = wb.y;
        Bs[lk + 2][lr] = wb.z; Bs[lk + 3][lr] = wb.w;
        __syncthreads();
#pragma unroll
        for (int kk = 0; kk < 8; kk++) {
            float a[8], bb[8];
            *(float4*)&a[0]  = *(const float4*)&As[kk][ty * 8];
            *(float4*)&a[4]  = *(const float4*)&As[kk][ty * 8 + 4];
            *(float4*)&bb[0] = *(const float4*)&Bs[kk][tx * 8];
            *(float4*)&bb[4] = *(const float4*)&Bs[kk][tx * 8 + 4];
#pragma unroll
            for (int i = 0; i < 8; i++)
#pragma unroll
                for (int j = 0; j < 8; j++)
                    acc[i][j] += a[i] * bb[j];
        }
        __syncthreads();
    }

#pragma unroll
    for (int i = 0; i < 8; i++) {
        const int qq = q0 + ty * 8 + i;
#pragma unroll
        for (int j = 0; j < 8; j++) {
            const int kk2 = n0 + tx * 8 + j;
            float v = acc[i][j] * 0.125f;  // 1/sqrt(64)
            if (mask[(size_t)b * SQ * SQ + (size_t)qq * SQ + kk2] == 0) v = 1e-9f;
            att[((size_t)bh * SQ + qq) * SQ + kk2] = v;
        }
    }
}

// ============================================================
// Row softmax in place. 1 block per row (2048 elems), 256 threads.
// ============================================================
__global__ __launch_bounds__(256)
void softmax_kernel(float* __restrict__ att)
{
    const size_t row = blockIdx.x;
    float* p = att + row * (size_t)SQ;
    const int tid = threadIdx.x;

    float4 v0 = ((const float4*)p)[tid];
    float4 v1 = ((const float4*)p)[tid + 256];

    float mx = fmaxf(fmaxf(fmaxf(v0.x, v0.y), fmaxf(v0.z, v0.w)),
                     fmaxf(fmaxf(v1.x, v1.y), fmaxf(v1.z, v1.w)));
    __shared__ float red[8];
    __shared__ float bcast;
#pragma unroll
    for (int o = 16; o > 0; o >>= 1) mx = fmaxf(mx, __shfl_xor_sync(0xffffffffu, mx, o));
    if ((tid & 31) == 0) red[tid >> 5] = mx;
    __syncthreads();
    if (tid == 0) {
        float m = red[0];
#pragma unroll
        for (int w = 1; w < 8; w++) m = fmaxf(m, red[w]);
        bcast = m;
    }
    __syncthreads();
    const float m = bcast;
    __syncthreads();   // protect red/bcast reuse

    v0.x = __expf(v0.x - m); v0.y = __expf(v0.y - m);
    v0.z = __expf(v0.z - m); v0.w = __expf(v0.w - m);
    v1.x = __expf(v1.x - m); v1.y = __expf(v1.y - m);
    v1.z = __expf(v1.z - m); v1.w = __expf(v1.w - m);
    float s = v0.x + v0.y + v0.z + v0.w + v1.x + v1.y + v1.z + v1.w;
#pragma unroll
    for (int o = 16; o > 0; o >>= 1) s += __shfl_xor_sync(0xffffffffu, s, o);
    if ((tid & 31) == 0) red[tid >> 5] = s;
    __syncthreads();
    if (tid == 0) {
        float t = 0.0f;
#pragma unroll
        for (int w = 0; w < 8; w++) t += red[w];
        bcast = 1.0f / t;
    }
    __syncthreads();
    const float inv = bcast;

    v0.x *= inv; v0.y *= inv; v0.z *= inv; v0.w *= inv;
    v1.x *= inv; v1.y *= inv; v1.z *= inv; v1.w *= inv;
    ((float4*)p)[tid] = v0;
    ((float4*)p)[tid + 256] = v1;
}

// ============================================================
// ctx[b,q,h*64+d] = sum_k att[bh,q,k] * Vh[bh,k,d]
// BM=128, BN=64(=DKH), BK=16, 256 threads, 8x4 per thread.
// ============================================================
__global__ __launch_bounds__(256, 2)
void pv_kernel(const float* __restrict__ att)
{
    __shared__ float As[16][128];
    __shared__ float Vs[16][64];
    const int tid = threadIdx.x;
    const int tx = tid & 15;
    const int ty = tid >> 4;
    const int bh = blockIdx.y;
    const int b = bh / NH, h = bh % NH;
    const int q0 = blockIdx.x * 128;
    const float* A = att + ((size_t)bh * SQ + q0) * SQ;
    const float* V = g_vh + (size_t)bh * SQ * DKH;

    const int lrA = tid >> 1;         // 0..127 (q row)
    const int lkA = (tid & 1) * 8;    // 0 or 8
    const int lrV = tid >> 4;         // 0..15 (k row)
    const int lcV = (tid & 15) * 4;   // 0..60

    float acc[8][4];
#pragma unroll
    for (int i = 0; i < 8; i++)
#pragma unroll
        for (int j = 0; j < 4; j++) acc[i][j] = 0.0f;

    for (int k0 = 0; k0 < SQ; k0 += 16) {
        float4 a0 = *(const float4*)(A + (size_t)lrA * SQ + k0 + lkA);
        float4 a1 = *(const float4*)(A + (size_t)lrA * SQ + k0 + lkA + 4);
        *(float4*)&Vs[lrV][lcV] = *(const float4*)(V + (size_t)(k0 + lrV) * DKH + lcV);
        As[lkA + 0][lrA] = a0.x; As[lkA + 1][lrA] = a0.y;
        As[lkA + 2][lrA] = a0.z; As[lkA + 3][lrA] = a0.w;
        As[lkA + 4][lrA] = a1.x; As[lkA + 5][lrA] = a1.y;
        As[lkA + 6][lrA] = a1.z; As[lkA + 7][lrA] = a1.w;
        __syncthreads();
#pragma unroll
        for (int kk = 0; kk < 16; kk++) {
            float a[8], bv[4];
            *(float4*)&a[0]  = *(const float4*)&As[kk][ty * 8];
            *(float4*)&a[4]  = *(const float4*)&As[kk][ty * 8 + 4];
            *(float4*)&bv[0] = *(const float4*)&Vs[kk][tx * 4];
#pragma unroll
            for (int i = 0; i < 8; i++)
#pragma unroll
                for (int j = 0; j < 4; j++)
                    acc[i][j] += a[i] * bv[j];
        }
        __syncthreads();
    }

#pragma unroll
    for (int i = 0; i < 8; i++) {
        const int q = q0 + ty * 8 + i;
#pragma unroll
        for (int j = 0; j < 4; j++) {
            const int d = tx * 4 + j;
            g_ctx[((size_t)b * SQ + q) * DM + h * DKH + d] = acc[i][j];
        }
    }
}

// ============================================================
extern "C" void kernel_launch(void* const* d_in, const int* in_sizes, int n_in,
                              void* d_out, int out_size)
{
    const float* q    = (const float*)d_in[0];
    const float* k    = (const float*)d_in[1];
    const float* v    = (const float*)d_in[2];
    const int*   mask = (const int*)  d_in[3];
    const float* Wq   = (const float*)d_in[4];
    const float* bq   = (const float*)d_in[5];
    const float* Wk   = (const float*)d_in[6];
    const float* bk   = (const float*)d_in[7];
    const float* Wv   = (const float*)d_in[8];
    const float* bv   = (const float*)d_in[9];
    const float* Wo   = (const float*)d_in[10];
    const float* bo   = (const float*)d_in[11];

    float *qh, *kh, *vh, *ctx, *attscr;
    cudaGetSymbolAddress((void**)&qh,     g_qh);
    cudaGetSymbolAddress((void**)&kh,     g_kh);
    cudaGetSymbolAddress((void**)&vh,     g_vh);
    cudaGetSymbolAddress((void**)&ctx,    g_ctx);
    cudaGetSymbolAddress((void**)&attscr, g_att_scratch);

    const long OUT_ELEMS = (long)NB * SQ * DM;            // 4,194,304
    const long ATT_ELEMS = (long)NBH * SQ * (long)SQ;     // 134,217,728
    float* outp = (float*)d_out;
    float* attp;
    if ((long)out_size >= OUT_ELEMS + ATT_ELEMS) {
        attp = outp + OUT_ELEMS;                 // (output, attention) concatenated
    } else if ((long)out_size == ATT_ELEMS) {
        attp = outp;                              // attention-only output
        outp = qh;                                // final proj result discarded (qh dead by then)
    } else {
        attp = attscr;                            // output-only: attention to scratch
    }

    const dim3 gProj(DM / 128, (NB * SQ) / 128); // (8, 32)
    sgemm_xwt<1><<<gProj, 256>>>(q, Wq, bq, qh, NB * SQ, DM, DM);
    sgemm_xwt<1><<<gProj, 256>>>(k, Wk, bk, kh, NB * SQ, DM, DM);
    sgemm_xwt<1><<<gProj, 256>>>(v, Wv, bv, vh, NB * SQ, DM, DM);

    scores_kernel<<<dim3(SQ / 128, SQ / 128, NBH), 256>>>(mask, attp); // (16,16,32)
    softmax_kernel<<<NBH * SQ, 256>>>(attp);                            // 65536 rows
    pv_kernel<<<dim3(SQ / 128, NBH), 256>>>(attp);                      // (16,32)

    sgemm_xwt<0><<<gProj, 256>>>(ctx, Wo, bo, outp, NB * SQ, DM, DM);
}

// round 5
// speedup vs baseline: 2.2636x; 2.2595x over previous
#include <cuda_runtime.h>
#include <cuda_bf16.h>
#include <cuda_fp16.h>
#include <cstdint>

#define SQ 2048
#define NB 2
#define NH 16
#define DKH 64
#define DM 1024
#define NBH (NB * NH)

static const size_t XN = (size_t)NB * SQ * DM;    // 4,194,304
static const size_t WN = (size_t)DM * DM;         // 1,048,576
#define AN ((size_t)NBH * SQ * SQ)                // 134,217,728

// ---------------- device scratch (alloc-free) ----------------
__device__ __nv_bfloat16 g_q_hi[XN],  g_q_lo[XN];
__device__ __nv_bfloat16 g_k_hi[XN],  g_k_lo[XN];
__device__ __nv_bfloat16 g_v_hi[XN],  g_v_lo[XN];
__device__ __nv_bfloat16 g_wq_hi[WN], g_wq_lo[WN];
__device__ __nv_bfloat16 g_wk_hi[WN], g_wk_lo[WN];
__device__ __nv_bfloat16 g_wv_hi[WN], g_wv_lo[WN];
__device__ __nv_bfloat16 g_wo_hi[WN], g_wo_lo[WN];
__device__ __nv_bfloat16 g_qh_hi[XN], g_qh_lo[XN];   // [bh, s, d]
__device__ __nv_bfloat16 g_kh_hi[XN], g_kh_lo[XN];   // [bh, s, d]
__device__ __half        g_vt[XN];                   // [bh, d, s] fp16
__device__ __nv_bfloat16 g_ctx_hi[XN], g_ctx_lo[XN]; // [b*s, h*d]
__device__ float g_att_scratch[AN];
__device__ float g_dummy_out[XN];

// ---------------- helpers ----------------
template <class A, class B> struct is_same_t { static const bool v = false; };
template <class A> struct is_same_t<A, A> { static const bool v = true; };

__device__ __forceinline__ uint32_t smem_u32(const void* p) {
    uint32_t a;
    asm("{ .reg .u64 t; cvta.to.shared.u64 t, %1; cvt.u32.u64 %0, t; }" : "=r"(a) : "l"(p));
    return a;
}
__device__ __forceinline__ void cpa16(uint32_t s, const void* g) {
    asm volatile("cp.async.ca.shared.global [%0], [%1], 16;" :: "r"(s), "l"(g));
}
__device__ __forceinline__ void cpa_commit() { asm volatile("cp.async.commit_group;"); }
__device__ __forceinline__ void cpa_wait1()  { asm volatile("cp.async.wait_group 1;"); }

__device__ __forceinline__ void ldm4(uint32_t d[4], uint32_t addr) {
    asm volatile("ldmatrix.sync.aligned.m8n8.x4.shared.b16 {%0,%1,%2,%3}, [%4];"
                 : "=r"(d[0]), "=r"(d[1]), "=r"(d[2]), "=r"(d[3]) : "r"(addr));
}
template <bool BF16>
__device__ __forceinline__ void mma16816(float c[4], const uint32_t a[4],
                                         uint32_t b0, uint32_t b1) {
    if (BF16)
        asm volatile(
            "mma.sync.aligned.m16n8k16.row.col.f32.bf16.bf16.f32 "
            "{%0,%1,%2,%3}, {%4,%5,%6,%7}, {%8,%9}, {%0,%1,%2,%3};"
            : "+f"(c[0]), "+f"(c[1]), "+f"(c[2]), "+f"(c[3])
            : "r"(a[0]), "r"(a[1]), "r"(a[2]), "r"(a[3]), "r"(b0), "r"(b1));
    else
        asm volatile(
            "mma.sync.aligned.m16n8k16.row.col.f32.f16.f16.f32 "
            "{%0,%1,%2,%3}, {%4,%5,%6,%7}, {%8,%9}, {%0,%1,%2,%3};"
            : "+f"(c[0]), "+f"(c[1]), "+f"(c[2]), "+f"(c[3])
            : "r"(a[0]), "r"(a[1]), "r"(a[2]), "r"(a[3]), "r"(b0), "r"(b1));
}
__device__ __forceinline__ uint32_t pack_bf2(float v0, float v1) {
    __nv_bfloat16 h0 = __float2bfloat16(v0), h1 = __float2bfloat16(v1);
    return (uint32_t)__bfloat16_as_ushort(h0) | ((uint32_t)__bfloat16_as_ushort(h1) << 16);
}

// ============================================================
// MMA GEMM: C[128 x BN] = A[128 x K] * B[BN x K]^T  (both row stride K)
// SPLIT=3: A,B given as (hi,lo) bf16, 3-mma compensated product.
// SPLIT=1: single mma on hi arrays (T dtype).
// ACONV=1: A is fp32 in gmem, converted to fp16 on the fly.
// MODE 0: proj Q/K -> bf16 hi/lo scatter [bh,s,d]  (+bias)
// MODE 1: proj V   -> fp16 [bh,d,s] (transpose)    (+bias)
// MODE 2: out proj -> fp32 [m, DM]                 (+bias)
// MODE 3: scores   -> fp32 att[z,q,k], *0.125, mask
// MODE 4: PV       -> bf16 hi/lo ctx [b*SQ+q, h*64+d]
// ============================================================
template <int BN, int MODE, int SPLIT, int ACONV, typename T>
__global__ __launch_bounds__(256, 2)
void mma_gemm(const T* __restrict__ Ah_g, const T* __restrict__ Al_g,
              const float* __restrict__ Af_g,
              const T* __restrict__ Bh_g, const T* __restrict__ Bl_g,
              const float* __restrict__ bias, const int* __restrict__ mask,
              float* __restrict__ outf, uint32_t* __restrict__ ohi,
              uint32_t* __restrict__ olo,
              int K, size_t sAz, size_t sBz)
{
    constexpr bool BF16 = is_same_t<T, __nv_bfloat16>::v;
    constexpr int BM = 128, BK = 32;
    constexpr int STR = BK + 24;              // 56 halves = 112B row stride (16B aligned, ldmatrix conflict-free)
    constexpr int ASZ = BM * STR * 2;         // 14336 B
    constexpr int BSZ = BN * STR * 2;
    constexpr int NPART = (SPLIT == 3) ? 2 : 1;
    constexpr int OFF_AH = 0;
    constexpr int OFF_BH = ASZ * NPART;
    constexpr int STG = (ASZ + BSZ) * NPART;
    constexpr int NSPAN = BN / 2;
    constexpr int NT = NSPAN / 8;

    extern __shared__ char smem[];
    const uint32_t sb = smem_u32(smem);
    const int tid = threadIdx.x;
    const int lane = tid & 31, wid = tid >> 5;
    const int wm = wid & 3, wn = wid >> 2;

    const int m0 = blockIdx.y * BM;
    const int n0 = blockIdx.x * BN;
    const int z  = blockIdx.z;
    const T* pAh = Ah_g ? Ah_g + (size_t)z * sAz : nullptr;
    const T* pAl = Al_g ? Al_g + (size_t)z * sAz : nullptr;
    const float* pAf = Af_g ? Af_g + (size_t)z * sAz : nullptr;
    const T* pBh = Bh_g + (size_t)z * sBz;
    const T* pBl = Bl_g ? Bl_g + (size_t)z * sBz : nullptr;

    const int NCH = K / BK;

    // ----- async issue of one K-chunk into a stage -----
    auto issue = [&](int c, int st) {
        const int kb = c * BK;
        const uint32_t base = sb + st * STG;
        if (!ACONV) {
#pragma unroll
            for (int j = 0; j < 2; j++) {
                int u = tid + j * 256, r = u >> 2, c8 = u & 3;
                cpa16(base + OFF_AH + r * 112 + c8 * 16,
                      pAh + (size_t)(m0 + r) * K + kb + c8 * 8);
                if (SPLIT == 3)
                    cpa16(base + OFF_AH + ASZ + r * 112 + c8 * 16,
                          pAl + (size_t)(m0 + r) * K + kb + c8 * 8);
            }
        }
#pragma unroll
        for (int j = 0; j < (BN == 128 ? 2 : 1); j++) {
            int u = tid + j * 256, r = u >> 2, c8 = u & 3;
            cpa16(base + OFF_BH + r * 112 + c8 * 16,
                  pBh + (size_t)(n0 + r) * K + kb + c8 * 8);
            if (SPLIT == 3)
                cpa16(base + OFF_BH + BSZ + r * 112 + c8 * 16,
                      pBl + (size_t)(n0 + r) * K + kb + c8 * 8);
        }
    };

    // ----- ACONV: fp32 A loads + convert/store -----
    float4 rA[4];
    auto loadA = [&](int c) {
        const int kb = c * BK;
#pragma unroll
        for (int j = 0; j < 4; j++) {
            int u = tid + j * 256, r = u >> 3, c4 = u & 7;
            rA[j] = *(const float4*)(pAf + (size_t)(m0 + r) * K + kb + c4 * 4);
        }
    };
    auto storeA = [&](int st) {
        char* base = smem + st * STG + OFF_AH;
#pragma unroll
        for (int j = 0; j < 4; j++) {
            int u = tid + j * 256, r = u >> 3, c4 = u & 7;
            __half2 h0 = __floats2half2_rn(rA[j].x, rA[j].y);
            __half2 h1 = __floats2half2_rn(rA[j].z, rA[j].w);
            *(int2*)(base + r * 112 + c4 * 8) =
                make_int2(*(int*)&h0, *(int*)&h1);
        }
    };

    float acc[2][NT][4];
#pragma unroll
    for (int a = 0; a < 2; a++)
#pragma unroll
        for (int b = 0; b < NT; b++)
#pragma unroll
            for (int c = 0; c < 4; c++) acc[a][b][c] = 0.0f;

    // prologue
    issue(0, 0); cpa_commit();
    if (NCH > 1) issue(1, 1);
    cpa_commit();
    if (ACONV) { loadA(0); storeA(0); }

    for (int c = 0; c < NCH; c++) {
        const int st = c & 1;
        cpa_wait1();
        __syncthreads();
        if (ACONV && c + 1 < NCH) loadA(c + 1);

        const uint32_t aBase = sb + st * STG + OFF_AH;
        const char*    bBase = smem + st * STG + OFF_BH;
#pragma unroll
        for (int ks = 0; ks < 2; ks++) {
            const int kb = ks * 16;
            uint32_t ah[2][4], al[2][4];
#pragma unroll
            for (int mt = 0; mt < 2; mt++) {
                uint32_t ad = aBase + (wm * 32 + mt * 16 + (lane & 15)) * 112
                              + ((kb + ((lane >> 4) << 3)) << 1);
                ldm4(ah[mt], ad);
                if (SPLIT == 3) ldm4(al[mt], ad + ASZ);
            }
#pragma unroll
            for (int nt = 0; nt < NT; nt++) {
                const int nrow = wn * NSPAN + nt * 8 + (lane >> 2);
                const char* bp = bBase + nrow * 112 + ((kb + (lane & 3) * 2) << 1);
                uint32_t bh0 = *(const uint32_t*)bp;
                uint32_t bh1 = *(const uint32_t*)(bp + 16);
#pragma unroll
                for (int mt = 0; mt < 2; mt++)
                    mma16816<BF16>(acc[mt][nt], ah[mt], bh0, bh1);
                if (SPLIT == 3) {
                    uint32_t bl0 = *(const uint32_t*)(bp + BSZ);
                    uint32_t bl1 = *(const uint32_t*)(bp + BSZ + 16);
#pragma unroll
                    for (int mt = 0; mt < 2; mt++) {
                        mma16816<BF16>(acc[mt][nt], ah[mt], bl0, bl1);
                        mma16816<BF16>(acc[mt][nt], al[mt], bh0, bh1);
                    }
                }
            }
        }
        __syncthreads();
        if (ACONV && c + 1 < NCH) storeA((c + 1) & 1);
        if (c + 2 < NCH) issue(c + 2, st);
        cpa_commit();
    }

    // ---------------- epilogue ----------------
    float (*sf)[129] = (float(*)[129])smem;   // MODE1 staging (reuses pipeline smem)

#pragma unroll
    for (int mt = 0; mt < 2; mt++)
#pragma unroll
        for (int nt = 0; nt < NT; nt++)
#pragma unroll
            for (int hh = 0; hh < 2; hh++) {
                float v0 = acc[mt][nt][hh * 2 + 0];
                float v1 = acc[mt][nt][hh * 2 + 1];
                const int m_loc = wm * 32 + mt * 16 + (lane >> 2) + hh * 8;
                const int n_loc = wn * NSPAN + nt * 8 + (lane & 3) * 2;
                const int gm = m0 + m_loc, gn = n0 + n_loc;

                if (MODE == 0) {
                    v0 += bias[gn]; v1 += bias[gn + 1];
                    const int b = gm >> 11, s = gm & 2047, h = gn >> 6, d = gn & 63;
                    const size_t a = ((((size_t)(b * NH + h)) * SQ + s) * DKH + d) >> 1;
                    ohi[a] = pack_bf2(v0, v1);
                    olo[a] = pack_bf2(v0 - __bfloat162float(__float2bfloat16(v0)),
                                      v1 - __bfloat162float(__float2bfloat16(v1)));
                } else if (MODE == 2) {
                    v0 += bias[gn]; v1 += bias[gn + 1];
                    *(float2*)&outf[(size_t)gm * DM + gn] = make_float2(v0, v1);
                } else if (MODE == 3) {
                    v0 *= 0.125f; v1 *= 0.125f;
                    const size_t midx = ((size_t)(z >> 4) * SQ + gm) * SQ + gn;
                    int2 mv = *(const int2*)(mask + midx);
                    if (mv.x == 0) v0 = 1e-9f;
                    if (mv.y == 0) v1 = 1e-9f;
                    *(float2*)&outf[((size_t)z * SQ + gm) * SQ + gn] = make_float2(v0, v1);
                } else if (MODE == 4) {
                    const int b = z >> 4, h = z & 15;
                    const size_t a = (((size_t)(b * SQ + gm)) * DM + h * DKH + gn) >> 1;
                    ohi[a] = pack_bf2(v0, v1);
                    olo[a] = pack_bf2(v0 - __bfloat162float(__float2bfloat16(v0)),
                                      v1 - __bfloat162float(__float2bfloat16(v1)));
                } else { // MODE 1: stage for transpose
                    sf[m_loc][n_loc]     = v0 + bias[gn];
                    sf[m_loc][n_loc + 1] = v1 + bias[gn + 1];
                }
            }

    if (MODE == 1) {
        __syncthreads();
        const int b = m0 >> 11, s0 = m0 & 2047;
#pragma unroll
        for (int it = 0; it < 16; it++) {
            const int rn = it * 8 + wid;            // local n row
            const int gn = n0 + rn;
            const int h = gn >> 6, d = gn & 63;
            uint32_t* orow = ohi + ((((size_t)(b * NH + h)) * DKH + d) * SQ + s0) / 2;
#pragma unroll
            for (int j = 0; j < 2; j++) {
                const int sp = j * 64 + 2 * lane;
                __half2 hv = __floats2half2_rn(sf[sp][rn], sf[sp + 1][rn]);
                orow[j * 32 + lane] = *(uint32_t*)&hv;
            }
        }
    }
}

// ---------------- fp32 -> bf16 hi/lo split ----------------
__global__ __launch_bounds__(256)
void cvt_split(const float* __restrict__ x, __nv_bfloat16* __restrict__ hi,
               __nv_bfloat16* __restrict__ lo, size_t n4)
{
    size_t i = (size_t)blockIdx.x * blockDim.x + threadIdx.x;
    if (i >= n4) return;
    float4 v = ((const float4*)x)[i];
    float f[4] = {v.x, v.y, v.z, v.w};
    uint32_t h[4], l[4];
#pragma unroll
    for (int j = 0; j < 4; j++) {
        __nv_bfloat16 hb = __float2bfloat16(f[j]);
        h[j] = (uint32_t)__bfloat16_as_ushort(hb);
        l[j] = (uint32_t)__bfloat16_as_ushort(__float2bfloat16(f[j] - __bfloat162float(hb)));
    }
    ((int2*)hi)[i] = make_int2((int)(h[0] | (h[1] << 16)), (int)(h[2] | (h[3] << 16)));
    ((int2*)lo)[i] = make_int2((int)(l[0] | (l[1] << 16)), (int)(l[2] | (l[3] << 16)));
}

// ---------------- row softmax (in place, fp32) ----------------
__global__ __launch_bounds__(256)
void softmax_kernel(float* __restrict__ att)
{
    const size_t row = blockIdx.x;
    float* p = att + row * (size_t)SQ;
    const int tid = threadIdx.x;
    float4 v0 = ((const float4*)p)[tid];
    float4 v1 = ((const float4*)p)[tid + 256];
    float mx = fmaxf(fmaxf(fmaxf(v0.x, v0.y), fmaxf(v0.z, v0.w)),
                     fmaxf(fmaxf(v1.x, v1.y), fmaxf(v1.z, v1.w)));
    __shared__ float red[8];
    __shared__ float bcast;
#pragma unroll
    for (int o = 16; o > 0; o >>= 1) mx = fmaxf(mx, __shfl_xor_sync(0xffffffffu, mx, o));
    if ((tid & 31) == 0) red[tid >> 5] = mx;
    __syncthreads();
    if (tid == 0) {
        float m = red[0];
#pragma unroll
        for (int w = 1; w < 8; w++) m = fmaxf(m, red[w]);
        bcast = m;
    }
    __syncthreads();
    const float m = bcast;
    __syncthreads();
    v0.x = __expf(v0.x - m); v0.y = __expf(v0.y - m);
    v0.z = __expf(v0.z - m); v0.w = __expf(v0.w - m);
    v1.x = __expf(v1.x - m); v1.y = __expf(v1.y - m);
    v1.z = __expf(v1.z - m); v1.w = __expf(v1.w - m);
    float s = v0.x + v0.y + v0.z + v0.w + v1.x + v1.y + v1.z + v1.w;
#pragma unroll
    for (int o = 16; o > 0; o >>= 1) s += __shfl_xor_sync(0xffffffffu, s, o);
    if ((tid & 31) == 0) red[tid >> 5] = s;
    __syncthreads();
    if (tid == 0) {
        float t = 0.0f;
#pragma unroll
        for (int w = 0; w < 8; w++) t += red[w];
        bcast = 1.0f / t;
    }
    __syncthreads();
    const float inv = bcast;
    v0.x *= inv; v0.y *= inv; v0.z *= inv; v0.w *= inv;
    v1.x *= inv; v1.y *= inv; v1.z *= inv; v1.w *= inv;
    ((float4*)p)[tid] = v0;
    ((float4*)p)[tid + 256] = v1;
}

// ============================================================
extern "C" void kernel_launch(void* const* d_in, const int* in_sizes, int n_in,
                              void* d_out, int out_size)
{
    const float* q    = (const float*)d_in[0];
    const float* k    = (const float*)d_in[1];
    const float* v    = (const float*)d_in[2];
    const int*   mask = (const int*)  d_in[3];
    const float* Wq   = (const float*)d_in[4];
    const float* bq   = (const float*)d_in[5];
    const float* Wk   = (const float*)d_in[6];
    const float* bk   = (const float*)d_in[7];
    const float* Wv   = (const float*)d_in[8];
    const float* bv   = (const float*)d_in[9];
    const float* Wo   = (const float*)d_in[10];
    const float* bo   = (const float*)d_in[11];

    __nv_bfloat16 *q_hi, *q_lo, *k_hi, *k_lo, *v_hi, *v_lo;
    __nv_bfloat16 *wq_hi, *wq_lo, *wk_hi, *wk_lo, *wv_hi, *wv_lo, *wo_hi, *wo_lo;
    __nv_bfloat16 *qh_hi, *qh_lo, *kh_hi, *kh_lo, *cx_hi, *cx_lo;
    __half *vt;
    float *attscr, *dummy;
    cudaGetSymbolAddress((void**)&q_hi,  g_q_hi);  cudaGetSymbolAddress((void**)&q_lo,  g_q_lo);
    cudaGetSymbolAddress((void**)&k_hi,  g_k_hi);  cudaGetSymbolAddress((void**)&k_lo,  g_k_lo);
    cudaGetSymbolAddress((void**)&v_hi,  g_v_hi);  cudaGetSymbolAddress((void**)&v_lo,  g_v_lo);
    cudaGetSymbolAddress((void**)&wq_hi, g_wq_hi); cudaGetSymbolAddress((void**)&wq_lo, g_wq_lo);
    cudaGetSymbolAddress((void**)&wk_hi, g_wk_hi); cudaGetSymbolAddress((void**)&wk_lo, g_wk_lo);
    cudaGetSymbolAddress((void**)&wv_hi, g_wv_hi); cudaGetSymbolAddress((void**)&wv_lo, g_wv_lo);
    cudaGetSymbolAddress((void**)&wo_hi, g_wo_hi); cudaGetSymbolAddress((void**)&wo_lo, g_wo_lo);
    cudaGetSymbolAddress((void**)&qh_hi, g_qh_hi); cudaGetSymbolAddress((void**)&qh_lo, g_qh_lo);
    cudaGetSymbolAddress((void**)&kh_hi, g_kh_hi); cudaGetSymbolAddress((void**)&kh_lo, g_kh_lo);
    cudaGetSymbolAddress((void**)&vt,    g_vt);
    cudaGetSymbolAddress((void**)&cx_hi, g_ctx_hi); cudaGetSymbolAddress((void**)&cx_lo, g_ctx_lo);
    cudaGetSymbolAddress((void**)&attscr, g_att_scratch);
    cudaGetSymbolAddress((void**)&dummy,  g_dummy_out);

    const long OUT_ELEMS = (long)NB * SQ * DM;
    const long ATT_ELEMS = (long)AN;
    float* outp = (float*)d_out;
    float* attp;
    if ((long)out_size >= OUT_ELEMS + ATT_ELEMS)      attp = outp + OUT_ELEMS;
    else if ((long)out_size == ATT_ELEMS) { attp = outp; outp = dummy; }
    else                                               attp = attscr;

    // smem sizes: STG = (ASZ+BSZ)*NPART, 2 stages
    constexpr int SM_S3_128 = 2 * (14336 * 2 + 128 * 56 * 2 * 2);  // 114688
    constexpr int SM_S1_64  = 2 * (14336 + 64 * 56 * 2);           // 43008

    cudaFuncSetAttribute(mma_gemm<128, 0, 3, 0, __nv_bfloat16>,
                         cudaFuncAttributeMaxDynamicSharedMemorySize, SM_S3_128);
    cudaFuncSetAttribute(mma_gemm<128, 1, 3, 0, __nv_bfloat16>,
                         cudaFuncAttributeMaxDynamicSharedMemorySize, SM_S3_128);
    cudaFuncSetAttribute(mma_gemm<128, 2, 3, 0, __nv_bfloat16>,
                         cudaFuncAttributeMaxDynamicSharedMemorySize, SM_S3_128);
    cudaFuncSetAttribute(mma_gemm<128, 3, 3, 0, __nv_bfloat16>,
                         cudaFuncAttributeMaxDynamicSharedMemorySize, SM_S3_128);
    cudaFuncSetAttribute(mma_gemm<64, 4, 1, 1, __half>,
                         cudaFuncAttributeMaxDynamicSharedMemorySize, SM_S1_64);

    // splits
    cvt_split<<<(int)(XN / 4 / 256), 256>>>(q, q_hi, q_lo, XN / 4);
    cvt_split<<<(int)(XN / 4 / 256), 256>>>(k, k_hi, k_lo, XN / 4);
    cvt_split<<<(int)(XN / 4 / 256), 256>>>(v, v_hi, v_lo, XN / 4);
    cvt_split<<<(int)(WN / 4 / 256), 256>>>(Wq, wq_hi, wq_lo, WN / 4);
    cvt_split<<<(int)(WN / 4 / 256), 256>>>(Wk, wk_hi, wk_lo, WN / 4);
    cvt_split<<<(int)(WN / 4 / 256), 256>>>(Wv, wv_hi, wv_lo, WN / 4);
    cvt_split<<<(int)(WN / 4 / 256), 256>>>(Wo, wo_hi, wo_lo, WN / 4);

    // projections (M=4096, N=1024, K=1024)
    mma_gemm<128, 0, 3, 0, __nv_bfloat16><<<dim3(8, 32, 1), 256, SM_S3_128>>>(
        q_hi, q_lo, nullptr, wq_hi, wq_lo, bq, nullptr, nullptr,
        (uint32_t*)qh_hi, (uint32_t*)qh_lo, DM, 0, 0);
    mma_gemm<128, 0, 3, 0, __nv_bfloat16><<<dim3(8, 32, 1), 256, SM_S3_128>>>(
        k_hi, k_lo, nullptr, wk_hi, wk_lo, bk, nullptr, nullptr,
        (uint32_t*)kh_hi, (uint32_t*)kh_lo, DM, 0, 0);
    mma_gemm<128, 1, 3, 0, __nv_bfloat16><<<dim3(8, 32, 1), 256, SM_S3_128>>>(
        v_hi, v_lo, nullptr, wv_hi, wv_lo, bv, nullptr, nullptr,
        (uint32_t*)vt, nullptr, DM, 0, 0);

    // scores: per bh, 128q x 128k tiles, K=64
    mma_gemm<128, 3, 3, 0, __nv_bfloat16><<<dim3(16, 16, NBH), 256, SM_S3_128>>>(
        qh_hi, qh_lo, nullptr, kh_hi, kh_lo, nullptr, mask, attp, nullptr, nullptr,
        DKH, (size_t)SQ * DKH, (size_t)SQ * DKH);

    softmax_kernel<<<NBH * SQ, 256>>>(attp);

    // PV: A = fp32 probs (converted), B = vt fp16 [d][s], K=2048
    mma_gemm<64, 4, 1, 1, __half><<<dim3(1, 16, NBH), 256, SM_S1_64>>>(
        nullptr, nullptr, attp, vt, nullptr, nullptr, nullptr, nullptr,
        (uint32_t*)cx_hi, (uint32_t*)cx_lo, SQ, (size_t)SQ * SQ, (size_t)DKH * SQ);

    // output projection
    mma_gemm<128, 2, 3, 0, __nv_bfloat16><<<dim3(8, 32, 1), 256, SM_S3_128>>>(
        cx_hi, cx_lo, nullptr, wo_hi, wo_lo, bo, nullptr, outp, nullptr, nullptr,
        DM, 0, 0);
}

// round 6
// speedup vs baseline: 2.6687x; 1.1789x over previous
#include <cuda_runtime.h>
#include <cuda_bf16.h>
#include <cuda_fp16.h>
#include <cstdint>

#define SQ 2048
#define NB 2
#define NH 16
#define DKH 64
#define DM 1024
#define NBH (NB * NH)

static const size_t XN = (size_t)NB * SQ * DM;    // 4,194,304
static const size_t WN = (size_t)DM * DM;         // 1,048,576
#define AN ((size_t)NBH * SQ * SQ)                // 134,217,728

// ---------------- device scratch (alloc-free) ----------------
__device__ __nv_bfloat16 g_q_hi[XN],  g_q_lo[XN];
__device__ __nv_bfloat16 g_k_hi[XN],  g_k_lo[XN];
__device__ __nv_bfloat16 g_v_hi[XN],  g_v_lo[XN];
__device__ __nv_bfloat16 g_wq_hi[WN], g_wq_lo[WN];
__device__ __nv_bfloat16 g_wk_hi[WN], g_wk_lo[WN];
__device__ __nv_bfloat16 g_wv_hi[WN], g_wv_lo[WN];
__device__ __nv_bfloat16 g_wo_hi[WN], g_wo_lo[WN];
__device__ __nv_bfloat16 g_qh_hi[XN], g_qh_lo[XN];   // [bh, s, d]
__device__ __nv_bfloat16 g_kh_hi[XN], g_kh_lo[XN];   // [bh, s, d]
__device__ __half        g_vt[XN];                   // [bh, d, s] fp16
__device__ __nv_bfloat16 g_ctx_hi[XN], g_ctx_lo[XN]; // [b*s, h*d]
__device__ float2 g_stats[(size_t)NBH * 16 * SQ];    // per-tile (max, sumexp)
__device__ float2 g_rowstat[(size_t)NBH * SQ];       // per-row (max, 1/sum)
__device__ float g_att_scratch[AN];
__device__ float g_dummy_out[XN];

// ---------------- helpers ----------------
template <class A, class B> struct is_same_t { static const bool v = false; };
template <class A> struct is_same_t<A, A> { static const bool v = true; };

__device__ __forceinline__ uint32_t smem_u32(const void* p) {
    uint32_t a;
    asm("{ .reg .u64 t; cvta.to.shared.u64 t, %1; cvt.u32.u64 %0, t; }" : "=r"(a) : "l"(p));
    return a;
}
__device__ __forceinline__ void cpa16(uint32_t s, const void* g) {
    asm volatile("cp.async.ca.shared.global [%0], [%1], 16;" :: "r"(s), "l"(g));
}
__device__ __forceinline__ void cpa_commit() { asm volatile("cp.async.commit_group;"); }
__device__ __forceinline__ void cpa_wait1()  { asm volatile("cp.async.wait_group 1;"); }

__device__ __forceinline__ void ldm4(uint32_t d[4], uint32_t addr) {
    asm volatile("ldmatrix.sync.aligned.m8n8.x4.shared.b16 {%0,%1,%2,%3}, [%4];"
                 : "=r"(d[0]), "=r"(d[1]), "=r"(d[2]), "=r"(d[3]) : "r"(addr));
}
template <bool BF16>
__device__ __forceinline__ void mma16816(float c[4], const uint32_t a[4],
                                         uint32_t b0, uint32_t b1) {
    if (BF16)
        asm volatile(
            "mma.sync.aligned.m16n8k16.row.col.f32.bf16.bf16.f32 "
            "{%0,%1,%2,%3}, {%4,%5,%6,%7}, {%8,%9}, {%0,%1,%2,%3};"
            : "+f"(c[0]), "+f"(c[1]), "+f"(c[2]), "+f"(c[3])
            : "r"(a[0]), "r"(a[1]), "r"(a[2]), "r"(a[3]), "r"(b0), "r"(b1));
    else
        asm volatile(
            "mma.sync.aligned.m16n8k16.row.col.f32.f16.f16.f32 "
            "{%0,%1,%2,%3}, {%4,%5,%6,%7}, {%8,%9}, {%0,%1,%2,%3};"
            : "+f"(c[0]), "+f"(c[1]), "+f"(c[2]), "+f"(c[3])
            : "r"(a[0]), "r"(a[1]), "r"(a[2]), "r"(a[3]), "r"(b0), "r"(b1));
}
__device__ __forceinline__ uint32_t pack_bf2(float v0, float v1) {
    __nv_bfloat16 h0 = __float2bfloat16(v0), h1 = __float2bfloat16(v1);
    return (uint32_t)__bfloat16_as_ushort(h0) | ((uint32_t)__bfloat16_as_ushort(h1) << 16);
}

// ============================================================
// MMA GEMM: C[128 x BN] = A[128 x K] * B[BN x K]^T  (rows stride K)
// SPLIT=3: (hi,lo) bf16 3-mma compensated.  SPLIT=1: single mma (T).
// ACONV=1: A fp32 in gmem; MODE4 applies softmax normalize using rowstat
//          and writes normalized p back to att (outf) in-place.
// MODE 0: proj Q/K -> bf16 hi/lo scatter [bh,s,d]  (+bias)
// MODE 1: proj V   -> fp16 [bh,d,s] (transpose)    (+bias)
// MODE 2: out proj -> fp32 [m, DM]                 (+bias)
// MODE 3: scores   -> fp32 att[z,q,k] (*0.125, mask) + tile row stats
// MODE 4: fused softmax-normalize + PV -> bf16 hi/lo ctx
// ============================================================
template <int BN, int MODE, int SPLIT, int ACONV, typename T>
__global__ __launch_bounds__(256, 2)
void mma_gemm(const T* __restrict__ Ah_g, const T* __restrict__ Al_g,
              const float* __restrict__ Af_g,
              const T* __restrict__ Bh_g, const T* __restrict__ Bl_g,
              const float* __restrict__ bias, const int* __restrict__ mask,
              float* __restrict__ outf, uint32_t* __restrict__ ohi,
              uint32_t* __restrict__ olo,
              float2* __restrict__ stats, const float2* __restrict__ rowstat,
              int K, size_t sAz, size_t sBz)
{
    constexpr bool BF16 = is_same_t<T, __nv_bfloat16>::v;
    constexpr int BM = 128, BK = 32;
    constexpr int STR = 40;                   // halves; 80B rows (banks r*20%32 distinct)
    constexpr int ASZ = BM * STR * 2;         // 10240 B
    constexpr int BSZ = BN * STR * 2;
    constexpr int NPART = (SPLIT == 3) ? 2 : 1;
    constexpr int OFF_BH = ASZ * NPART;
    constexpr int STG = (ASZ + BSZ) * NPART;
    constexpr int NSPAN = BN / 2;
    constexpr int NT = NSPAN / 8;

    extern __shared__ char smem[];
    const uint32_t sb = smem_u32(smem);
    const int tid = threadIdx.x;
    const int lane = tid & 31, wid = tid >> 5;
    const int wm = wid & 3, wn = wid >> 2;

    const int m0 = blockIdx.y * BM;
    const int n0 = blockIdx.x * BN;
    const int z  = blockIdx.z;
    const T* pAh = Ah_g ? Ah_g + (size_t)z * sAz : nullptr;
    const T* pAl = Al_g ? Al_g + (size_t)z * sAz : nullptr;
    const float* pAf = Af_g ? Af_g + (size_t)z * sAz : nullptr;
    float* pW = (MODE == 4) ? outf + (size_t)z * sAz : nullptr;
    const T* pBh = Bh_g + (size_t)z * sBz;
    const T* pBl = Bl_g ? Bl_g + (size_t)z * sBz : nullptr;

    const int NCH = K / BK;

    // row stats for MODE 4 (rows fixed per thread across chunks)
    float2 rs[4];
    if (ACONV && MODE == 4) {
#pragma unroll
        for (int j = 0; j < 4; j++)
            rs[j] = rowstat[(size_t)z * SQ + m0 + ((tid + j * 256) >> 3)];
    }

    // ----- async issue of one K-chunk into a stage -----
    auto issue = [&](int c, int st) {
        const int kb = c * BK;
        const uint32_t base = sb + st * STG;
        if (!ACONV) {
#pragma unroll
            for (int j = 0; j < 2; j++) {
                int u = tid + j * 256, r = u >> 2, c8 = u & 3;
                cpa16(base + r * 80 + c8 * 16,
                      pAh + (size_t)(m0 + r) * K + kb + c8 * 8);
                if (SPLIT == 3)
                    cpa16(base + ASZ + r * 80 + c8 * 16,
                          pAl + (size_t)(m0 + r) * K + kb + c8 * 8);
            }
        }
#pragma unroll
        for (int j = 0; j < (BN == 128 ? 2 : 1); j++) {
            int u = tid + j * 256, r = u >> 2, c8 = u & 3;
            cpa16(base + OFF_BH + r * 80 + c8 * 16,
                  pBh + (size_t)(n0 + r) * K + kb + c8 * 8);
            if (SPLIT == 3)
                cpa16(base + OFF_BH + BSZ + r * 80 + c8 * 16,
                      pBl + (size_t)(n0 + r) * K + kb + c8 * 8);
        }
    };

    // ----- ACONV: fp32 A loads + (normalize) + convert/store -----
    float4 rA[4];
    auto loadA = [&](int c) {
        const int kb = c * BK;
#pragma unroll
        for (int j = 0; j < 4; j++) {
            int u = tid + j * 256, r = u >> 3, c4 = u & 7;
            rA[j] = *(const float4*)(pAf + (size_t)(m0 + r) * K + kb + c4 * 4);
        }
    };
    auto storeA = [&](int c) {
        const int st = c & 1, kb = c * BK;
        char* base = smem + st * STG;
#pragma unroll
        for (int j = 0; j < 4; j++) {
            int u = tid + j * 256, r = u >> 3, c4 = u & 7;
            float4 p = rA[j];
            if (MODE == 4) {
                p.x = __expf(p.x - rs[j].x) * rs[j].y;
                p.y = __expf(p.y - rs[j].x) * rs[j].y;
                p.z = __expf(p.z - rs[j].x) * rs[j].y;
                p.w = __expf(p.w - rs[j].x) * rs[j].y;
                *(float4*)(pW + (size_t)(m0 + r) * K + kb + c4 * 4) = p;
            }
            __half2 h0 = __floats2half2_rn(p.x, p.y);
            __half2 h1 = __floats2half2_rn(p.z, p.w);
            *(int2*)(base + r * 80 + c4 * 8) = make_int2(*(int*)&h0, *(int*)&h1);
        }
    };

    float acc[2][NT][4];
#pragma unroll
    for (int a = 0; a < 2; a++)
#pragma unroll
        for (int b = 0; b < NT; b++)
#pragma unroll
            for (int c = 0; c < 4; c++) acc[a][b][c] = 0.0f;

    // prologue
    issue(0, 0); cpa_commit();
    if (NCH > 1) issue(1, 1);
    cpa_commit();
    if (ACONV) { loadA(0); storeA(0); }

    for (int c = 0; c < NCH; c++) {
        const int st = c & 1;
        cpa_wait1();
        __syncthreads();
        if (ACONV && c + 1 < NCH) loadA(c + 1);

        const uint32_t aBase = sb + st * STG;
        const uint32_t bBase = aBase + OFF_BH;
#pragma unroll
        for (int ks = 0; ks < 2; ks++) {
            uint32_t ah[2][4], al[2][4];
#pragma unroll
            for (int mt = 0; mt < 2; mt++) {
                uint32_t ad = aBase + (wm * 32 + mt * 16 + (lane & 15)) * 80
                              + ks * 32 + ((lane >> 4) << 4);
                ldm4(ah[mt], ad);
                if (SPLIT == 3) ldm4(al[mt], ad + ASZ);
            }
            const int g = lane >> 3;
            const int nsub = (g >> 1) * 8, khalf = (g & 1) * 16;
#pragma unroll
            for (int ntp = 0; ntp < NT / 2; ntp++) {
                uint32_t bd = bBase
                    + (wn * NSPAN + ntp * 16 + nsub + (lane & 7)) * 80
                    + ks * 32 + khalf;
                uint32_t bh[4];
                ldm4(bh, bd);
#pragma unroll
                for (int mt = 0; mt < 2; mt++) {
                    mma16816<BF16>(acc[mt][2 * ntp],     ah[mt], bh[0], bh[1]);
                    mma16816<BF16>(acc[mt][2 * ntp + 1], ah[mt], bh[2], bh[3]);
                }
                if (SPLIT == 3) {
                    uint32_t bl[4];
                    ldm4(bl, bd + BSZ);
#pragma unroll
                    for (int mt = 0; mt < 2; mt++) {
                        mma16816<BF16>(acc[mt][2 * ntp],     ah[mt], bl[0], bl[1]);
                        mma16816<BF16>(acc[mt][2 * ntp + 1], ah[mt], bl[2], bl[3]);
                        mma16816<BF16>(acc[mt][2 * ntp],     al[mt], bh[0], bh[1]);
                        mma16816<BF16>(acc[mt][2 * ntp + 1], al[mt], bh[2], bh[3]);
                    }
                }
            }
        }
        __syncthreads();
        if (ACONV && c + 1 < NCH) storeA(c + 1);
        if (c + 2 < NCH) issue(c + 2, st);
        cpa_commit();
    }

    // ---------------- epilogue ----------------
    float (*sf)[129] = (float(*)[129])smem;   // MODE1 staging (pipeline smem reuse)

#pragma unroll
    for (int mt = 0; mt < 2; mt++)
#pragma unroll
        for (int nt = 0; nt < NT; nt++)
#pragma unroll
            for (int hh = 0; hh < 2; hh++) {
                float v0 = acc[mt][nt][hh * 2 + 0];
                float v1 = acc[mt][nt][hh * 2 + 1];
                const int m_loc = wm * 32 + mt * 16 + (lane >> 2) + hh * 8;
                const int n_loc = wn * NSPAN + nt * 8 + (lane & 3) * 2;
                const int gm = m0 + m_loc, gn = n0 + n_loc;

                if (MODE == 0) {
                    v0 += bias[gn]; v1 += bias[gn + 1];
                    const int b = gm >> 11, s = gm & 2047, h = gn >> 6, d = gn & 63;
                    const size_t a = ((((size_t)(b * NH + h)) * SQ + s) * DKH + d) >> 1;
                    ohi[a] = pack_bf2(v0, v1);
                    olo[a] = pack_bf2(v0 - __bfloat162float(__float2bfloat16(v0)),
                                      v1 - __bfloat162float(__float2bfloat16(v1)));
                } else if (MODE == 2) {
                    v0 += bias[gn]; v1 += bias[gn + 1];
                    *(float2*)&outf[(size_t)gm * DM + gn] = make_float2(v0, v1);
                } else if (MODE == 3) {
                    v0 *= 0.125f; v1 *= 0.125f;
                    const size_t midx = ((size_t)(z >> 4) * SQ + gm) * SQ + gn;
                    int2 mv = *(const int2*)(mask + midx);
                    if (mv.x == 0) v0 = 1e-9f;
                    if (mv.y == 0) v1 = 1e-9f;
                    acc[mt][nt][hh * 2 + 0] = v0;
                    acc[mt][nt][hh * 2 + 1] = v1;
                    *(float2*)&outf[((size_t)z * SQ + gm) * SQ + gn] = make_float2(v0, v1);
                } else if (MODE == 4) {
                    const int b = z >> 4, h = z & 15;
                    const size_t a = (((size_t)(b * SQ + gm)) * DM + h * DKH + gn) >> 1;
                    ohi[a] = pack_bf2(v0, v1);
                    olo[a] = pack_bf2(v0 - __bfloat162float(__float2bfloat16(v0)),
                                      v1 - __bfloat162float(__float2bfloat16(v1)));
                } else { // MODE 1: stage for transpose
                    sf[m_loc][n_loc]     = v0 + bias[gn];
                    sf[m_loc][n_loc + 1] = v1 + bias[gn + 1];
                }
            }

    if (MODE == 1) {
        __syncthreads();
        const int b = m0 >> 11, s0 = m0 & 2047;
#pragma unroll
        for (int it = 0; it < 16; it++) {
            const int rn = it * 8 + wid;            // local n row
            const int gn = n0 + rn;
            const int h = gn >> 6, d = gn & 63;
            uint32_t* orow = ohi + ((((size_t)(b * NH + h)) * DKH + d) * SQ + s0) / 2;
#pragma unroll
            for (int j = 0; j < 2; j++) {
                const int sp = j * 64 + 2 * lane;
                __half2 hv = __floats2half2_rn(sf[sp][rn], sf[sp + 1][rn]);
                orow[j * 32 + lane] = *(uint32_t*)&hv;
            }
        }
    }

    if (MODE == 3) {
        // per-tile row stats: max & sum of exp over this block's 128 columns
        float* smax = (float*)smem;           // [2 wn][128 rows]
        float* ssum = smax + 256;
#pragma unroll
        for (int mt = 0; mt < 2; mt++)
#pragma unroll
            for (int hh = 0; hh < 2; hh++) {
                float mx = -1e30f;
#pragma unroll
                for (int nt = 0; nt < NT; nt++)
                    mx = fmaxf(mx, fmaxf(acc[mt][nt][hh * 2], acc[mt][nt][hh * 2 + 1]));
                mx = fmaxf(mx, __shfl_xor_sync(0xffffffffu, mx, 1));
                mx = fmaxf(mx, __shfl_xor_sync(0xffffffffu, mx, 2));
                float sm = 0.0f;
#pragma unroll
                for (int nt = 0; nt < NT; nt++)
                    sm += __expf(acc[mt][nt][hh * 2] - mx) + __expf(acc[mt][nt][hh * 2 + 1] - mx);
                sm += __shfl_xor_sync(0xffffffffu, sm, 1);
                sm += __shfl_xor_sync(0xffffffffu, sm, 2);
                if ((lane & 3) == 0) {
                    const int m_loc = wm * 32 + mt * 16 + hh * 8 + (lane >> 2);
                    smax[wn * 128 + m_loc] = mx;
                    ssum[wn * 128 + m_loc] = sm;
                }
            }
        __syncthreads();
        if (tid < 128) {
            float ma = smax[tid], mb = smax[128 + tid];
            float sa = ssum[tid], sb2 = ssum[128 + tid];
            float M = fmaxf(ma, mb);
            float S = sa * __expf(ma - M) + sb2 * __expf(mb - M);
            stats[((size_t)z * 16 + blockIdx.x) * SQ + m0 + tid] = make_float2(M, S);
        }
    }
}

// ---------------- combine per-tile stats -> per-row (max, 1/sum) ----------------
__global__ __launch_bounds__(256)
void stats_reduce(const float2* __restrict__ stats, float2* __restrict__ rowstat)
{
    const int idx = blockIdx.x * 256 + threadIdx.x;    // 65536 rows
    const int bh = idx >> 11, q = idx & 2047;
    float2 t[16];
    float M = -1e30f;
#pragma unroll
    for (int kb = 0; kb < 16; kb++) {
        t[kb] = stats[((size_t)bh * 16 + kb) * SQ + q];
        M = fmaxf(M, t[kb].x);
    }
    float S = 0.0f;
#pragma unroll
    for (int kb = 0; kb < 16; kb++) S += t[kb].y * __expf(t[kb].x - M);
    rowstat[idx] = make_float2(M, 1.0f / S);
}

// ---------------- fp32 -> bf16 hi/lo split ----------------
__global__ __launch_bounds__(256)
void cvt_split(const float* __restrict__ x, __nv_bfloat16* __restrict__ hi,
               __nv_bfloat16* __restrict__ lo, size_t n4)
{
    size_t i = (size_t)blockIdx.x * blockDim.x + threadIdx.x;
    if (i >= n4) return;
    float4 v = ((const float4*)x)[i];
    float f[4] = {v.x, v.y, v.z, v.w};
    uint32_t h[4], l[4];
#pragma unroll
    for (int j = 0; j < 4; j++) {
        __nv_bfloat16 hb = __float2bfloat16(f[j]);
        h[j] = (uint32_t)__bfloat16_as_ushort(hb);
        l[j] = (uint32_t)__bfloat16_as_ushort(__float2bfloat16(f[j] - __bfloat162float(hb)));
    }
    ((int2*)hi)[i] = make_int2((int)(h[0] | (h[1] << 16)), (int)(h[2] | (h[3] << 16)));
    ((int2*)lo)[i] = make_int2((int)(l[0] | (l[1] << 16)), (int)(l[2] | (l[3] << 16)));
}

// ============================================================
extern "C" void kernel_launch(void* const* d_in, const int* in_sizes, int n_in,
                              void* d_out, int out_size)
{
    const float* q    = (const float*)d_in[0];
    const float* k    = (const float*)d_in[1];
    const float* v    = (const float*)d_in[2];
    const int*   mask = (const int*)  d_in[3];
    const float* Wq   = (const float*)d_in[4];
    const float* bq   = (const float*)d_in[5];
    const float* Wk   = (const float*)d_in[6];
    const float* bk   = (const float*)d_in[7];
    const float* Wv   = (const float*)d_in[8];
    const float* bv   = (const float*)d_in[9];
    const float* Wo   = (const float*)d_in[10];
    const float* bo   = (const float*)d_in[11];

    __nv_bfloat16 *q_hi, *q_lo, *k_hi, *k_lo, *v_hi, *v_lo;
    __nv_bfloat16 *wq_hi, *wq_lo, *wk_hi, *wk_lo, *wv_hi, *wv_lo, *wo_hi, *wo_lo;
    __nv_bfloat16 *qh_hi, *qh_lo, *kh_hi, *kh_lo, *cx_hi, *cx_lo;
    __half *vt;
    float *attscr, *dummy;
    float2 *statsp, *rowstatp;
    cudaGetSymbolAddress((void**)&q_hi,  g_q_hi);  cudaGetSymbolAddress((void**)&q_lo,  g_q_lo);
    cudaGetSymbolAddress((void**)&k_hi,  g_k_hi);  cudaGetSymbolAddress((void**)&k_lo,  g_k_lo);
    cudaGetSymbolAddress((void**)&v_hi,  g_v_hi);  cudaGetSymbolAddress((void**)&v_lo,  g_v_lo);
    cudaGetSymbolAddress((void**)&wq_hi, g_wq_hi); cudaGetSymbolAddress((void**)&wq_lo, g_wq_lo);
    cudaGetSymbolAddress((void**)&wk_hi, g_wk_hi); cudaGetSymbolAddress((void**)&wk_lo, g_wk_lo);
    cudaGetSymbolAddress((void**)&wv_hi, g_wv_hi); cudaGetSymbolAddress((void**)&wv_lo, g_wv_lo);
    cudaGetSymbolAddress((void**)&wo_hi, g_wo_hi); cudaGetSymbolAddress((void**)&wo_lo, g_wo_lo);
    cudaGetSymbolAddress((void**)&qh_hi, g_qh_hi); cudaGetSymbolAddress((void**)&qh_lo, g_qh_lo);
    cudaGetSymbolAddress((void**)&kh_hi, g_kh_hi); cudaGetSymbolAddress((void**)&kh_lo, g_kh_lo);
    cudaGetSymbolAddress((void**)&vt,    g_vt);
    cudaGetSymbolAddress((void**)&cx_hi, g_ctx_hi); cudaGetSymbolAddress((void**)&cx_lo, g_ctx_lo);
    cudaGetSymbolAddress((void**)&attscr, g_att_scratch);
    cudaGetSymbolAddress((void**)&dummy,  g_dummy_out);
    cudaGetSymbolAddress((void**)&statsp, g_stats);
    cudaGetSymbolAddress((void**)&rowstatp, g_rowstat);

    const long OUT_ELEMS = (long)NB * SQ * DM;
    const long ATT_ELEMS = (long)AN;
    float* outp = (float*)d_out;
    float* attp;
    if ((long)out_size >= OUT_ELEMS + ATT_ELEMS)      attp = outp + OUT_ELEMS;
    else if ((long)out_size == ATT_ELEMS) { attp = outp; outp = dummy; }
    else                                               attp = attscr;

    // smem: STG = (ASZ+BSZ)*NPART, 2 stages; STR=40 -> ASZ/BSZ128 = 10240
    constexpr int SM_S3_128 = 2 * ((10240 + 10240) * 2);  // 81920
    constexpr int SM_S1_64  = 2 * (10240 + 5120);          // 30720

    cudaFuncSetAttribute(mma_gemm<128, 0, 3, 0, __nv_bfloat16>,
                         cudaFuncAttributeMaxDynamicSharedMemorySize, SM_S3_128);
    cudaFuncSetAttribute(mma_gemm<128, 1, 3, 0, __nv_bfloat16>,
                         cudaFuncAttributeMaxDynamicSharedMemorySize, SM_S3_128);
    cudaFuncSetAttribute(mma_gemm<128, 2, 3, 0, __nv_bfloat16>,
                         cudaFuncAttributeMaxDynamicSharedMemorySize, SM_S3_128);
    cudaFuncSetAttribute(mma_gemm<128, 3, 3, 0, __nv_bfloat16>,
                         cudaFuncAttributeMaxDynamicSharedMemorySize, SM_S3_128);
    cudaFuncSetAttribute(mma_gemm<64, 4, 1, 1, __half>,
                         cudaFuncAttributeMaxDynamicSharedMemorySize, SM_S1_64);

    // splits
    cvt_split<<<(int)(XN / 4 / 256), 256>>>(q, q_hi, q_lo, XN / 4);
    cvt_split<<<(int)(XN / 4 / 256), 256>>>(k, k_hi, k_lo, XN / 4);
    cvt_split<<<(int)(XN / 4 / 256), 256>>>(v, v_hi, v_lo, XN / 4);
    cvt_split<<<(int)(WN / 4 / 256), 256>>>(Wq, wq_hi, wq_lo, WN / 4);
    cvt_split<<<(int)(WN / 4 / 256), 256>>>(Wk, wk_hi, wk_lo, WN / 4);
    cvt_split<<<(int)(WN / 4 / 256), 256>>>(Wv, wv_hi, wv_lo, WN / 4);
    cvt_split<<<(int)(WN / 4 / 256), 256>>>(Wo, wo_hi, wo_lo, WN / 4);

    // projections (M=4096, N=1024, K=1024)
    mma_gemm<128, 0, 3, 0, __nv_bfloat16><<<dim3(8, 32, 1), 256, SM_S3_128>>>(
        q_hi, q_lo, nullptr, wq_hi, wq_lo, bq, nullptr, nullptr,
        (uint32_t*)qh_hi, (uint32_t*)qh_lo, nullptr, nullptr, DM, 0, 0);
    mma_gemm<128, 0, 3, 0, __nv_bfloat16><<<dim3(8, 32, 1), 256, SM_S3_128>>>(
        k_hi, k_lo, nullptr, wk_hi, wk_lo, bk, nullptr, nullptr,
        (uint32_t*)kh_hi, (uint32_t*)kh_lo, nullptr, nullptr, DM, 0, 0);
    mma_gemm<128, 1, 3, 0, __nv_bfloat16><<<dim3(8, 32, 1), 256, SM_S3_128>>>(
        v_hi, v_lo, nullptr, wv_hi, wv_lo, bv, nullptr, nullptr,
        (uint32_t*)vt, nullptr, nullptr, nullptr, DM, 0, 0);

    // scores: raw masked/scaled scores + per-tile row stats
    mma_gemm<128, 3, 3, 0, __nv_bfloat16><<<dim3(16, 16, NBH), 256, SM_S3_128>>>(
        qh_hi, qh_lo, nullptr, kh_hi, kh_lo, nullptr, mask, attp, nullptr, nullptr,
        statsp, nullptr, DKH, (size_t)SQ * DKH, (size_t)SQ * DKH);

    stats_reduce<<<NBH * SQ / 256, 256>>>(statsp, rowstatp);

    // fused normalize + PV: reads raw scores, writes p in-place, MMA p*V
    mma_gemm<64, 4, 1, 1, __half><<<dim3(1, 16, NBH), 256, SM_S1_64>>>(
        nullptr, nullptr, attp, vt, nullptr, nullptr, nullptr, attp,
        (uint32_t*)cx_hi, (uint32_t*)cx_lo, nullptr, rowstatp,
        SQ, (size_t)SQ * SQ, (size_t)DKH * SQ);

    // output projection
    mma_gemm<128, 2, 3, 0, __nv_bfloat16><<<dim3(8, 32, 1), 256, SM_S3_128>>>(
        cx_hi, cx_lo, nullptr, wo_hi, wo_lo, bo, nullptr, outp, nullptr, nullptr,
        nullptr, nullptr, DM, 0, 0);
}

// round 7
// speedup vs baseline: 3.4732x; 1.3015x over previous
#include <cuda_runtime.h>
#include <cuda_bf16.h>
#include <cuda_fp16.h>
#include <cstdint>

#define SQ 2048
#define NB 2
#define NH 16
#define DKH 64
#define DM 1024
#define NBH (NB * NH)

static const size_t XN = (size_t)NB * SQ * DM;    // 4,194,304
static const size_t WN = (size_t)DM * DM;         // 1,048,576
#define AN ((size_t)NBH * SQ * SQ)                // 134,217,728

// ---------------- device scratch (alloc-free) ----------------
__device__ __half        g_xq[XN], g_xk[XN], g_xv[XN];     // fp16 inputs
__device__ __half        g_wq[WN], g_wk[WN], g_wv[WN];     // fp16 weights
__device__ __nv_bfloat16 g_wo_hi[WN], g_wo_lo[WN];         // Wo split bf16
__device__ __half        g_qh[XN], g_kh[XN];               // [bh, s, d] fp16
__device__ __half        g_vt[XN];                         // [bh, d, s] fp16
__device__ __nv_bfloat16 g_ctx_hi[XN], g_ctx_lo[XN];       // [b*s, h*d]
__device__ float2 g_stats[(size_t)NBH * 16 * SQ];          // per-tile (max, sumexp)
__device__ float2 g_rowstat[(size_t)NBH * SQ];             // per-row (max, 1/sum)
__device__ float g_att_scratch[AN];
__device__ float g_dummy_out[XN];

// ---------------- helpers ----------------
template <class A, class B> struct is_same_t { static const bool v = false; };
template <class A> struct is_same_t<A, A> { static const bool v = true; };

__device__ __forceinline__ uint32_t smem_u32(const void* p) {
    uint32_t a;
    asm("{ .reg .u64 t; cvta.to.shared.u64 t, %1; cvt.u32.u64 %0, t; }" : "=r"(a) : "l"(p));
    return a;
}
__device__ __forceinline__ void cpa16(uint32_t s, const void* g) {
    asm volatile("cp.async.ca.shared.global [%0], [%1], 16;" :: "r"(s), "l"(g));
}
__device__ __forceinline__ void cpa_commit() { asm volatile("cp.async.commit_group;"); }
template <int N>
__device__ __forceinline__ void cpa_waitg() {
    asm volatile("cp.async.wait_group %0;" :: "n"(N));
}
__device__ __forceinline__ void ldm4(uint32_t d[4], uint32_t addr) {
    asm volatile("ldmatrix.sync.aligned.m8n8.x4.shared.b16 {%0,%1,%2,%3}, [%4];"
                 : "=r"(d[0]), "=r"(d[1]), "=r"(d[2]), "=r"(d[3]) : "r"(addr));
}
template <bool BF16>
__device__ __forceinline__ void mma16816(float c[4], const uint32_t a[4],
                                         uint32_t b0, uint32_t b1) {
    if (BF16)
        asm volatile(
            "mma.sync.aligned.m16n8k16.row.col.f32.bf16.bf16.f32 "
            "{%0,%1,%2,%3}, {%4,%5,%6,%7}, {%8,%9}, {%0,%1,%2,%3};"
            : "+f"(c[0]), "+f"(c[1]), "+f"(c[2]), "+f"(c[3])
            : "r"(a[0]), "r"(a[1]), "r"(a[2]), "r"(a[3]), "r"(b0), "r"(b1));
    else
        asm volatile(
            "mma.sync.aligned.m16n8k16.row.col.f32.f16.f16.f32 "
            "{%0,%1,%2,%3}, {%4,%5,%6,%7}, {%8,%9}, {%0,%1,%2,%3};"
            : "+f"(c[0]), "+f"(c[1]), "+f"(c[2]), "+f"(c[3])
            : "r"(a[0]), "r"(a[1]), "r"(a[2]), "r"(a[3]), "r"(b0), "r"(b1));
}
__device__ __forceinline__ uint32_t pack_bf2(float v0, float v1) {
    __nv_bfloat16 h0 = __float2bfloat16(v0), h1 = __float2bfloat16(v1);
    return (uint32_t)__bfloat16_as_ushort(h0) | ((uint32_t)__bfloat16_as_ushort(h1) << 16);
}
__device__ __forceinline__ uint32_t pack_hf2(float v0, float v1) {
    __half2 h = __floats2half2_rn(v0, v1);
    return *(uint32_t*)&h;
}

// ============================================================
// MMA GEMM: C[128 x BN] = A[128 x K] * B[BN x K]^T  (rows stride K)
// SPLIT=3: (hi,lo) pairs, 3-mma compensated.  SPLIT=1: single mma.
// ACONV=1: A fp32 in gmem (MODE4: softmax-normalize via rowstat,
//          write normalized p back to att in-place, convert to fp16).
// NSTG: pipeline stages (one __syncthreads per chunk).
// MODE 0: proj Q/K -> fp16 scatter [bh,s,d]  (+bias)
// MODE 1: proj V   -> fp16 [bh,d,s] (transpose, +bias)
// MODE 2: out proj -> fp32 [m, DM]  (+bias)
// MODE 3: scores   -> fp32 att[z,q,k] (*0.125, mask) + tile row stats
// MODE 4: fused softmax-normalize + PV -> bf16 hi/lo ctx
// ============================================================
template <int BN, int MODE, int SPLIT, int ACONV, int NSTG, typename T>
__global__ __launch_bounds__(256, 2)
void mma_gemm(const T* __restrict__ Ah_g, const T* __restrict__ Al_g,
              const float* __restrict__ Af_g,
              const T* __restrict__ Bh_g, const T* __restrict__ Bl_g,
              const float* __restrict__ bias, const int* __restrict__ mask,
              float* __restrict__ outf, uint32_t* __restrict__ ohi,
              uint32_t* __restrict__ olo,
              float2* __restrict__ stats, const float2* __restrict__ rowstat,
              int K, size_t sAz, size_t sBz)
{
    constexpr bool BF16 = is_same_t<T, __nv_bfloat16>::v;
    constexpr int BM = 128, BK = 32;
    constexpr int ASZ = BM * 80;              // 80B rows (banks r*20%32 distinct)
    constexpr int BSZ = BN * 80;
    constexpr int NPART = (SPLIT == 3) ? 2 : 1;
    constexpr int OFF_BH = ASZ * NPART;
    constexpr int STG = (ASZ + BSZ) * NPART;
    constexpr int NSPAN = BN / 2;
    constexpr int NT = NSPAN / 8;

    extern __shared__ char smem[];
    const uint32_t sb = smem_u32(smem);
    const int tid = threadIdx.x;
    const int lane = tid & 31, wid = tid >> 5;
    const int wm = wid & 3, wn = wid >> 2;

    const int m0 = blockIdx.y * BM;
    const int n0 = blockIdx.x * BN;
    const int z  = blockIdx.z;
    const T* pAh = Ah_g ? Ah_g + (size_t)z * sAz : nullptr;
    const T* pAl = Al_g ? Al_g + (size_t)z * sAz : nullptr;
    const float* pAf = Af_g ? Af_g + (size_t)z * sAz : nullptr;
    float* pW = (MODE == 4) ? outf + (size_t)z * sAz : nullptr;
    const T* pBh = Bh_g + (size_t)z * sBz;
    const T* pBl = Bl_g ? Bl_g + (size_t)z * sBz : nullptr;

    const int NCH = K / BK;

    // row stats for MODE 4 (rows fixed per thread across chunks)
    float2 rs[4];
    if (ACONV && MODE == 4) {
#pragma unroll
        for (int j = 0; j < 4; j++)
            rs[j] = rowstat[(size_t)z * SQ + m0 + ((tid + j * 256) >> 3)];
    }

    // ----- async issue of one K-chunk into a stage -----
    auto issue = [&](int c, int st) {
        const int kb = c * BK;
        const uint32_t base = sb + st * STG;
        if (!ACONV) {
#pragma unroll
            for (int j = 0; j < 2; j++) {
                int u = tid + j * 256, r = u >> 2, c8 = u & 3;
                cpa16(base + r * 80 + c8 * 16,
                      pAh + (size_t)(m0 + r) * K + kb + c8 * 8);
                if (SPLIT == 3)
                    cpa16(base + ASZ + r * 80 + c8 * 16,
                          pAl + (size_t)(m0 + r) * K + kb + c8 * 8);
            }
        }
#pragma unroll
        for (int j = 0; j < (BN == 128 ? 2 : 1); j++) {
            int u = tid + j * 256, r = u >> 2, c8 = u & 3;
            cpa16(base + OFF_BH + r * 80 + c8 * 16,
                  pBh + (size_t)(n0 + r) * K + kb + c8 * 8);
            if (SPLIT == 3)
                cpa16(base + OFF_BH + BSZ + r * 80 + c8 * 16,
                      pBl + (size_t)(n0 + r) * K + kb + c8 * 8);
        }
    };

    // ----- ACONV: fp32 A loads + (normalize) + convert/store -----
    float4 rA[4];
    auto loadA = [&](int c) {
        const int kb = c * BK;
#pragma unroll
        for (int j = 0; j < 4; j++) {
            int u = tid + j * 256, r = u >> 3, c4 = u & 7;
            rA[j] = *(const float4*)(pAf + (size_t)(m0 + r) * K + kb + c4 * 4);
        }
    };
    auto storeA = [&](int c) {
        const int st = c % NSTG, kb = c * BK;
        char* base = smem + st * STG;
#pragma unroll
        for (int j = 0; j < 4; j++) {
            int u = tid + j * 256, r = u >> 3, c4 = u & 7;
            float4 p = rA[j];
            if (MODE == 4) {
                p.x = __expf(p.x - rs[j].x) * rs[j].y;
                p.y = __expf(p.y - rs[j].x) * rs[j].y;
                p.z = __expf(p.z - rs[j].x) * rs[j].y;
                p.w = __expf(p.w - rs[j].x) * rs[j].y;
                *(float4*)(pW + (size_t)(m0 + r) * K + kb + c4 * 4) = p;
            }
            __half2 h0 = __floats2half2_rn(p.x, p.y);
            __half2 h1 = __floats2half2_rn(p.z, p.w);
            *(int2*)(base + r * 80 + c4 * 8) = make_int2(*(int*)&h0, *(int*)&h1);
        }
    };

    float acc[2][NT][4];
#pragma unroll
    for (int a = 0; a < 2; a++)
#pragma unroll
        for (int b = 0; b < NT; b++)
#pragma unroll
            for (int c = 0; c < 4; c++) acc[a][b][c] = 0.0f;

    // prologue: issue chunks 0..NSTG-2
#pragma unroll
    for (int s = 0; s < NSTG - 1; s++) {
        if (s < NCH) issue(s, s);
        cpa_commit();
    }
    if (ACONV) { loadA(0); storeA(0); }

    for (int c = 0; c < NCH; c++) {
        const int st = c % NSTG;
        cpa_waitg<NSTG - 2>();
        __syncthreads();
        if (c + NSTG - 1 < NCH) issue(c + NSTG - 1, (c + NSTG - 1) % NSTG);
        cpa_commit();
        if (ACONV && c + 1 < NCH) loadA(c + 1);

        const uint32_t aBase = sb + st * STG;
        const uint32_t bBase = aBase + OFF_BH;
#pragma unroll
        for (int ks = 0; ks < 2; ks++) {
            uint32_t ah[2][4], al[2][4];
#pragma unroll
            for (int mt = 0; mt < 2; mt++) {
                uint32_t ad = aBase + (wm * 32 + mt * 16 + (lane & 15)) * 80
                              + ks * 32 + ((lane >> 4) << 4);
                ldm4(ah[mt], ad);
                if (SPLIT == 3) ldm4(al[mt], ad + ASZ);
            }
            const int g = lane >> 3;
            const int nsub = (g >> 1) * 8, khalf = (g & 1) * 16;
#pragma unroll
            for (int ntp = 0; ntp < NT / 2; ntp++) {
                uint32_t bd = bBase
                    + (wn * NSPAN + ntp * 16 + nsub + (lane & 7)) * 80
                    + ks * 32 + khalf;
                uint32_t bh[4];
                ldm4(bh, bd);
#pragma unroll
                for (int mt = 0; mt < 2; mt++) {
                    mma16816<BF16>(acc[mt][2 * ntp],     ah[mt], bh[0], bh[1]);
                    mma16816<BF16>(acc[mt][2 * ntp + 1], ah[mt], bh[2], bh[3]);
                }
                if (SPLIT == 3) {
                    uint32_t bl[4];
                    ldm4(bl, bd + BSZ);
#pragma unroll
                    for (int mt = 0; mt < 2; mt++) {
                        mma16816<BF16>(acc[mt][2 * ntp],     ah[mt], bl[0], bl[1]);
                        mma16816<BF16>(acc[mt][2 * ntp + 1], ah[mt], bl[2], bl[3]);
                        mma16816<BF16>(acc[mt][2 * ntp],     al[mt], bh[0], bh[1]);
                        mma16816<BF16>(acc[mt][2 * ntp + 1], al[mt], bh[2], bh[3]);
                    }
                }
            }
        }
        if (ACONV && c + 1 < NCH) storeA(c + 1);   // stage (c+1)%NSTG, free
    }
    __syncthreads();                                // protect smem reuse in epilogue

    // ---------------- epilogue ----------------
    float (*sf)[129] = (float(*)[129])smem;   // MODE1 staging

#pragma unroll
    for (int mt = 0; mt < 2; mt++)
#pragma unroll
        for (int nt = 0; nt < NT; nt++)
#pragma unroll
            for (int hh = 0; hh < 2; hh++) {
                float v0 = acc[mt][nt][hh * 2 + 0];
                float v1 = acc[mt][nt][hh * 2 + 1];
                const int m_loc = wm * 32 + mt * 16 + (lane >> 2) + hh * 8;
                const int n_loc = wn * NSPAN + nt * 8 + (lane & 3) * 2;
                const int gm = m0 + m_loc, gn = n0 + n_loc;

                if (MODE == 0) {
                    v0 += bias[gn]; v1 += bias[gn + 1];
                    const int b = gm >> 11, s = gm & 2047, h = gn >> 6, d = gn & 63;
                    const size_t a = ((((size_t)(b * NH + h)) * SQ + s) * DKH + d) >> 1;
                    ohi[a] = pack_hf2(v0, v1);
                } else if (MODE == 2) {
                    v0 += bias[gn]; v1 += bias[gn + 1];
                    *(float2*)&outf[(size_t)gm * DM + gn] = make_float2(v0, v1);
                } else if (MODE == 3) {
                    v0 *= 0.125f; v1 *= 0.125f;
                    const size_t midx = ((size_t)(z >> 4) * SQ + gm) * SQ + gn;
                    int2 mv = *(const int2*)(mask + midx);
                    if (mv.x == 0) v0 = 1e-9f;
                    if (mv.y == 0) v1 = 1e-9f;
                    acc[mt][nt][hh * 2 + 0] = v0;
                    acc[mt][nt][hh * 2 + 1] = v1;
                    *(float2*)&outf[((size_t)z * SQ + gm) * SQ + gn] = make_float2(v0, v1);
                } else if (MODE == 4) {
                    const int b = z >> 4, h = z & 15;
                    const size_t a = (((size_t)(b * SQ + gm)) * DM + h * DKH + gn) >> 1;
                    ohi[a] = pack_bf2(v0, v1);
                    olo[a] = pack_bf2(v0 - __bfloat162float(__float2bfloat16(v0)),
                                      v1 - __bfloat162float(__float2bfloat16(v1)));
                } else { // MODE 1: stage for transpose
                    sf[m_loc][n_loc]     = v0 + bias[gn];
                    sf[m_loc][n_loc + 1] = v1 + bias[gn + 1];
                }
            }

    if (MODE == 1) {
        __syncthreads();
        const int b = m0 >> 11, s0 = m0 & 2047;
#pragma unroll
        for (int it = 0; it < 16; it++) {
            const int rn = it * 8 + wid;            // local n row
            const int gn = n0 + rn;
            const int h = gn >> 6, d = gn & 63;
            uint32_t* orow = ohi + ((((size_t)(b * NH + h)) * DKH + d) * SQ + s0) / 2;
#pragma unroll
            for (int j = 0; j < 2; j++) {
                const int sp = j * 64 + 2 * lane;
                __half2 hv = __floats2half2_rn(sf[sp][rn], sf[sp + 1][rn]);
                orow[j * 32 + lane] = *(uint32_t*)&hv;
            }
        }
    }

    if (MODE == 3) {
        // per-tile row stats: max & sum of exp over this block's 128 columns
        float* smax = (float*)smem;           // [2 wn][128 rows]
        float* ssum = smax + 256;
#pragma unroll
        for (int mt = 0; mt < 2; mt++)
#pragma unroll
            for (int hh = 0; hh < 2; hh++) {
                float mx = -1e30f;
#pragma unroll
                for (int nt = 0; nt < NT; nt++)
                    mx = fmaxf(mx, fmaxf(acc[mt][nt][hh * 2], acc[mt][nt][hh * 2 + 1]));
                mx = fmaxf(mx, __shfl_xor_sync(0xffffffffu, mx, 1));
                mx = fmaxf(mx, __shfl_xor_sync(0xffffffffu, mx, 2));
                float sm = 0.0f;
#pragma unroll
                for (int nt = 0; nt < NT; nt++)
                    sm += __expf(acc[mt][nt][hh * 2] - mx) + __expf(acc[mt][nt][hh * 2 + 1] - mx);
                sm += __shfl_xor_sync(0xffffffffu, sm, 1);
                sm += __shfl_xor_sync(0xffffffffu, sm, 2);
                if ((lane & 3) == 0) {
                    const int m_loc = wm * 32 + mt * 16 + hh * 8 + (lane >> 2);
                    smax[wn * 128 + m_loc] = mx;
                    ssum[wn * 128 + m_loc] = sm;
                }
            }
        __syncthreads();
        if (tid < 128) {
            float ma = smax[tid], mb = smax[128 + tid];
            float sa = ssum[tid], sb2 = ssum[128 + tid];
            float M = fmaxf(ma, mb);
            float S = sa * __expf(ma - M) + sb2 * __expf(mb - M);
            stats[((size_t)z * 16 + blockIdx.x) * SQ + m0 + tid] = make_float2(M, S);
        }
    }
}

// ---------------- combine per-tile stats -> per-row (max, 1/sum) ----------------
__global__ __launch_bounds__(256)
void stats_reduce(const float2* __restrict__ stats, float2* __restrict__ rowstat)
{
    const int idx = blockIdx.x * 256 + threadIdx.x;    // 65536 rows
    const int bh = idx >> 11, q = idx & 2047;
    float2 t[16];
    float M = -1e30f;
#pragma unroll
    for (int kb = 0; kb < 16; kb++) {
        t[kb] = stats[((size_t)bh * 16 + kb) * SQ + q];
        M = fmaxf(M, t[kb].x);
    }
    float S = 0.0f;
#pragma unroll
    for (int kb = 0; kb < 16; kb++) S += t[kb].y * __expf(t[kb].x - M);
    rowstat[idx] = make_float2(M, 1.0f / S);
}

// ---------------- fp32 -> fp16 ----------------
__global__ __launch_bounds__(256)
void cvt_half(const float* __restrict__ x, __half* __restrict__ o, size_t n4)
{
    size_t i = (size_t)blockIdx.x * blockDim.x + threadIdx.x;
    if (i >= n4) return;
    float4 v = ((const float4*)x)[i];
    __half2 h0 = __floats2half2_rn(v.x, v.y);
    __half2 h1 = __floats2half2_rn(v.z, v.w);
    ((int2*)o)[i] = make_int2(*(int*)&h0, *(int*)&h1);
}

// ---------------- fp32 -> bf16 hi/lo split (Wo only) ----------------
__global__ __launch_bounds__(256)
void cvt_split(const float* __restrict__ x, __nv_bfloat16* __restrict__ hi,
               __nv_bfloat16* __restrict__ lo, size_t n4)
{
    size_t i = (size_t)blockIdx.x * blockDim.x + threadIdx.x;
    if (i >= n4) return;
    float4 v = ((const float4*)x)[i];
    float f[4] = {v.x, v.y, v.z, v.w};
    uint32_t h[4], l[4];
#pragma unroll
    for (int j = 0; j < 4; j++) {
        __nv_bfloat16 hb = __float2bfloat16(f[j]);
        h[j] = (uint32_t)__bfloat16_as_ushort(hb);
        l[j] = (uint32_t)__bfloat16_as_ushort(__float2bfloat16(f[j] - __bfloat162float(hb)));
    }
    ((int2*)hi)[i] = make_int2((int)(h[0] | (h[1] << 16)), (int)(h[2] | (h[3] << 16)));
    ((int2*)lo)[i] = make_int2((int)(l[0] | (l[1] << 16)), (int)(l[2] | (l[3] << 16)));
}

// ============================================================
extern "C" void kernel_launch(void* const* d_in, const int* in_sizes, int n_in,
                              void* d_out, int out_size)
{
    const float* q    = (const float*)d_in[0];
    const float* k    = (const float*)d_in[1];
    const float* v    = (const float*)d_in[2];
    const int*   mask = (const int*)  d_in[3];
    const float* Wq   = (const float*)d_in[4];
    const float* bq   = (const float*)d_in[5];
    const float* Wk   = (const float*)d_in[6];
    const float* bk   = (const float*)d_in[7];
    const float* Wv   = (const float*)d_in[8];
    const float* bv   = (const float*)d_in[9];
    const float* Wo   = (const float*)d_in[10];
    const float* bo   = (const float*)d_in[11];

    __half *xq, *xk, *xv, *wq, *wk, *wv, *qh, *kh, *vt;
    __nv_bfloat16 *wo_hi, *wo_lo, *cx_hi, *cx_lo;
    float *attscr, *dummy;
    float2 *statsp, *rowstatp;
    cudaGetSymbolAddress((void**)&xq, g_xq); cudaGetSymbolAddress((void**)&xk, g_xk);
    cudaGetSymbolAddress((void**)&xv, g_xv);
    cudaGetSymbolAddress((void**)&wq, g_wq); cudaGetSymbolAddress((void**)&wk, g_wk);
    cudaGetSymbolAddress((void**)&wv, g_wv);
    cudaGetSymbolAddress((void**)&wo_hi, g_wo_hi); cudaGetSymbolAddress((void**)&wo_lo, g_wo_lo);
    cudaGetSymbolAddress((void**)&qh, g_qh); cudaGetSymbolAddress((void**)&kh, g_kh);
    cudaGetSymbolAddress((void**)&vt, g_vt);
    cudaGetSymbolAddress((void**)&cx_hi, g_ctx_hi); cudaGetSymbolAddress((void**)&cx_lo, g_ctx_lo);
    cudaGetSymbolAddress((void**)&attscr, g_att_scratch);
    cudaGetSymbolAddress((void**)&dummy,  g_dummy_out);
    cudaGetSymbolAddress((void**)&statsp, g_stats);
    cudaGetSymbolAddress((void**)&rowstatp, g_rowstat);

    const long OUT_ELEMS = (long)NB * SQ * DM;
    const long ATT_ELEMS = (long)AN;
    float* outp = (float*)d_out;
    float* attp;
    if ((long)out_size >= OUT_ELEMS + ATT_ELEMS)      attp = outp + OUT_ELEMS;
    else if ((long)out_size == ATT_ELEMS) { attp = outp; outp = dummy; }
    else                                               attp = attscr;

    // smem: STG=(ASZ+BSZ)*NPART per stage
    constexpr int SM_P1_128 = 3 * (10240 + 10240);          // 61440 (split1, 3-stage)
    constexpr int SM_PROJV  = 66048;                         // max(61440, 128*129*4)
    constexpr int SM_PV     = 3 * (10240 + 5120);            // 46080
    constexpr int SM_S3_128 = 2 * ((10240 + 10240) * 2);     // 81920 (split3, 2-stage)

    cudaFuncSetAttribute(mma_gemm<128, 0, 1, 0, 3, __half>,
                         cudaFuncAttributeMaxDynamicSharedMemorySize, SM_P1_128);
    cudaFuncSetAttribute(mma_gemm<128, 1, 1, 0, 3, __half>,
                         cudaFuncAttributeMaxDynamicSharedMemorySize, SM_PROJV);
    cudaFuncSetAttribute(mma_gemm<128, 3, 1, 0, 3, __half>,
                         cudaFuncAttributeMaxDynamicSharedMemorySize, SM_P1_128);
    cudaFuncSetAttribute(mma_gemm<64, 4, 1, 1, 3, __half>,
                         cudaFuncAttributeMaxDynamicSharedMemorySize, SM_PV);
    cudaFuncSetAttribute(mma_gemm<128, 2, 3, 0, 2, __nv_bfloat16>,
                         cudaFuncAttributeMaxDynamicSharedMemorySize, SM_S3_128);

    // conversions
    cvt_half<<<(int)(XN / 4 / 256), 256>>>(q, xq, XN / 4);
    cvt_half<<<(int)(XN / 4 / 256), 256>>>(k, xk, XN / 4);
    cvt_half<<<(int)(XN / 4 / 256), 256>>>(v, xv, XN / 4);
    cvt_half<<<(int)(WN / 4 / 256), 256>>>(Wq, wq, WN / 4);
    cvt_half<<<(int)(WN / 4 / 256), 256>>>(Wk, wk, WN / 4);
    cvt_half<<<(int)(WN / 4 / 256), 256>>>(Wv, wv, WN / 4);
    cvt_split<<<(int)(WN / 4 / 256), 256>>>(Wo, wo_hi, wo_lo, WN / 4);

    // projections (M=4096, N=1024, K=1024), single fp16
    mma_gemm<128, 0, 1, 0, 3, __half><<<dim3(8, 32, 1), 256, SM_P1_128>>>(
        xq, nullptr, nullptr, wq, nullptr, bq, nullptr, nullptr,
        (uint32_t*)qh, nullptr, nullptr, nullptr, DM, 0, 0);
    mma_gemm<128, 0, 1, 0, 3, __half><<<dim3(8, 32, 1), 256, SM_P1_128>>>(
        xk, nullptr, nullptr, wk, nullptr, bk, nullptr, nullptr,
        (uint32_t*)kh, nullptr, nullptr, nullptr, DM, 0, 0);
    mma_gemm<128, 1, 1, 0, 3, __half><<<dim3(8, 32, 1), 256, SM_PROJV>>>(
        xv, nullptr, nullptr, wv, nullptr, bv, nullptr, nullptr,
        (uint32_t*)vt, nullptr, nullptr, nullptr, DM, 0, 0);

    // scores: raw masked/scaled scores + per-tile row stats (single fp16)
    mma_gemm<128, 3, 1, 0, 3, __half><<<dim3(16, 16, NBH), 256, SM_P1_128>>>(
        qh, nullptr, nullptr, kh, nullptr, nullptr, mask, attp, nullptr, nullptr,
        statsp, nullptr, DKH, (size_t)SQ * DKH, (size_t)SQ * DKH);

    stats_reduce<<<NBH * SQ / 256, 256>>>(statsp, rowstatp);

    // fused normalize + PV: reads raw scores, writes p in-place, MMA p*V
    mma_gemm<64, 4, 1, 1, 3, __half><<<dim3(1, 16, NBH), 256, SM_PV>>>(
        nullptr, nullptr, attp, vt, nullptr, nullptr, nullptr, attp,
        (uint32_t*)cx_hi, (uint32_t*)cx_lo, nullptr, rowstatp,
        SQ, (size_t)SQ * SQ, (size_t)DKH * SQ);

    // output projection (split-3 bf16 — precision on the dominant output)
    mma_gemm<128, 2, 3, 0, 2, __nv_bfloat16><<<dim3(8, 32, 1), 256, SM_S3_128>>>(
        cx_hi, cx_lo, nullptr, wo_hi, wo_lo, bo, nullptr, outp, nullptr, nullptr,
        nullptr, nullptr, DM, 0, 0);
}

// round 8
// speedup vs baseline: 3.7624x; 1.0833x over previous
#include <cuda_runtime.h>
#include <cuda_bf16.h>
#include <cuda_fp16.h>
#include <cstdint>

#define SQ 2048
#define NB 2
#define NH 16
#define DKH 64
#define DM 1024
#define NBH (NB * NH)

static const size_t XN = (size_t)NB * SQ * DM;    // 4,194,304
static const size_t WN = (size_t)DM * DM;         // 1,048,576
#define AN ((size_t)NBH * SQ * SQ)                // 134,217,728

// ---------------- device scratch (alloc-free) ----------------
__device__ __half        g_xq[XN], g_xk[XN], g_xv[XN];     // fp16 inputs
__device__ __half        g_wqkv[3 * WN];                   // fp16 weights, concat [3072,1024]
__device__ float         g_bqkv[3 * DM];                   // concat bias
__device__ __nv_bfloat16 g_wo_hi[WN], g_wo_lo[WN];         // Wo split bf16
__device__ __half        g_qh[XN], g_kh[XN];               // [bh, s, d] fp16
__device__ __half        g_vt[XN];                         // [bh, d, s] fp16
__device__ __nv_bfloat16 g_ctx_hi[XN], g_ctx_lo[XN];       // [b*s, h*d]
__device__ __half        g_pt[AN];                         // p_tile = exp(s - M_tile) fp16
__device__ float2 g_stats[(size_t)NBH * 16 * SQ];          // per-tile (max, sumexp)
__device__ float2 g_rowstat[(size_t)NBH * SQ];             // per-row (max, 1/sum)
__device__ float g_att_scratch[AN];
__device__ float g_dummy_out[XN];

// ---------------- helpers ----------------
template <class A, class B> struct is_same_t { static const bool v = false; };
template <class A> struct is_same_t<A, A> { static const bool v = true; };

__device__ __forceinline__ uint32_t smem_u32(const void* p) {
    uint32_t a;
    asm("{ .reg .u64 t; cvta.to.shared.u64 t, %1; cvt.u32.u64 %0, t; }" : "=r"(a) : "l"(p));
    return a;
}
__device__ __forceinline__ void cpa16(uint32_t s, const void* g) {
    asm volatile("cp.async.ca.shared.global [%0], [%1], 16;" :: "r"(s), "l"(g));
}
__device__ __forceinline__ void cpa_commit() { asm volatile("cp.async.commit_group;"); }
template <int N>
__device__ __forceinline__ void cpa_waitg() {
    asm volatile("cp.async.wait_group %0;" :: "n"(N));
}
__device__ __forceinline__ void ldm4(uint32_t d[4], uint32_t addr) {
    asm volatile("ldmatrix.sync.aligned.m8n8.x4.shared.b16 {%0,%1,%2,%3}, [%4];"
                 : "=r"(d[0]), "=r"(d[1]), "=r"(d[2]), "=r"(d[3]) : "r"(addr));
}
template <bool BF16>
__device__ __forceinline__ void mma16816(float c[4], const uint32_t a[4],
                                         uint32_t b0, uint32_t b1) {
    if (BF16)
        asm volatile(
            "mma.sync.aligned.m16n8k16.row.col.f32.bf16.bf16.f32 "
            "{%0,%1,%2,%3}, {%4,%5,%6,%7}, {%8,%9}, {%0,%1,%2,%3};"
            : "+f"(c[0]), "+f"(c[1]), "+f"(c[2]), "+f"(c[3])
            : "r"(a[0]), "r"(a[1]), "r"(a[2]), "r"(a[3]), "r"(b0), "r"(b1));
    else
        asm volatile(
            "mma.sync.aligned.m16n8k16.row.col.f32.f16.f16.f32 "
            "{%0,%1,%2,%3}, {%4,%5,%6,%7}, {%8,%9}, {%0,%1,%2,%3};"
            : "+f"(c[0]), "+f"(c[1]), "+f"(c[2]), "+f"(c[3])
            : "r"(a[0]), "r"(a[1]), "r"(a[2]), "r"(a[3]), "r"(b0), "r"(b1));
}
__device__ __forceinline__ uint32_t pack_bf2(float v0, float v1) {
    __nv_bfloat16 h0 = __float2bfloat16(v0), h1 = __float2bfloat16(v1);
    return (uint32_t)__bfloat16_as_ushort(h0) | ((uint32_t)__bfloat16_as_ushort(h1) << 16);
}
__device__ __forceinline__ uint32_t pack_hf2(float v0, float v1) {
    __half2 h = __floats2half2_rn(v0, v1);
    return *(uint32_t*)&h;
}

// ============================================================
// MMA GEMM: C[128 x BN] = A[128 x K] * B[BN x K]^T  (rows stride K)
// SPLIT=3: (hi,lo) pairs, 3-mma compensated.  SPLIT=1: single mma.
// ACONV=1 (MODE 4): A = p_t fp16 in gmem (Aux_g); scale by per-(row,tile)
//   exp(M_t - M) * invS, write normalized p fp32 to outf, feed fp16 to MMA.
// MODE 2: out proj -> fp32 [m, DM]  (+bias, split-3)
// MODE 3: scores   -> p_t fp16 [z,q,k] (*0.125, mask) + tile row stats
// MODE 4: normalize + PV -> att fp32 + bf16 hi/lo ctx
// MODE 5: merged QKV proj -> q/k fp16 scatter [bh,s,d], v fp16 [bh,d,s]
// ============================================================
template <int BN, int MODE, int SPLIT, int ACONV, int NSTG, typename T>
__global__ __launch_bounds__(256, 2)
void mma_gemm(const T* __restrict__ Ah_g, const T* __restrict__ Al_g,
              const void* __restrict__ Aux_g,
              const T* __restrict__ Bh_g, const T* __restrict__ Bl_g,
              const float* __restrict__ bias, const int* __restrict__ mask,
              float* __restrict__ outf, uint32_t* __restrict__ ohi,
              uint32_t* __restrict__ olo, uint32_t* __restrict__ ov,
              float2* __restrict__ stats, const float2* __restrict__ rowstat,
              const T* __restrict__ Ak_g, const T* __restrict__ Av_g,
              int K, size_t sAz, size_t sBz)
{
    constexpr bool BF16 = is_same_t<T, __nv_bfloat16>::v;
    constexpr int BM = 128, BK = 32;
    constexpr int ASZ = BM * 80;              // 80B rows (banks r*20%32 distinct)
    constexpr int BSZ = BN * 80;
    constexpr int NPART = (SPLIT == 3) ? 2 : 1;
    constexpr int OFF_BH = ASZ * NPART;
    constexpr int STG = (ASZ + BSZ) * NPART;
    constexpr int NSPAN = BN / 2;
    constexpr int NT = NSPAN / 8;

    extern __shared__ char smem[];
    const uint32_t sb = smem_u32(smem);
    const int tid = threadIdx.x;
    const int lane = tid & 31, wid = tid >> 5;
    const int wm = wid & 3, wn = wid >> 2;

    const int m0 = blockIdx.y * BM;
    const int n0 = blockIdx.x * BN;
    const int z  = blockIdx.z;
    const int sec = (MODE == 5) ? (n0 >> 10) : 0;

    const T* pAh = Ah_g ? Ah_g + (size_t)z * sAz : nullptr;
    if (MODE == 5) pAh = (sec == 0) ? Ah_g : (sec == 1) ? Ak_g : Av_g;
    const T* pAl = Al_g ? Al_g + (size_t)z * sAz : nullptr;
    const __half* pPt = (MODE == 4) ? (const __half*)Aux_g + (size_t)z * sAz : nullptr;
    float* pW = (MODE == 4) ? outf + (size_t)z * sAz : nullptr;
    const T* pBh = Bh_g + (size_t)z * sBz;
    const T* pBl = Bl_g ? Bl_g + (size_t)z * sBz : nullptr;

    const int NCH = K / BK;

    // MODE 4: per-row (max, invS), per-tile scale cache
    float2 rs[4];
    float sc[4];
    int cur_t = -1;
    if (MODE == 4) {
#pragma unroll
        for (int j = 0; j < 4; j++)
            rs[j] = rowstat[(size_t)z * SQ + m0 + (tid >> 3) + j * 32];
    }

    // ----- async issue of one K-chunk into a stage -----
    auto issue = [&](int c, int st) {
        const int kb = c * BK;
        const uint32_t base = sb + st * STG;
        if (!ACONV) {
#pragma unroll
            for (int j = 0; j < 2; j++) {
                int u = tid + j * 256, r = u >> 2, c8 = u & 3;
                cpa16(base + r * 80 + c8 * 16,
                      pAh + (size_t)(m0 + r) * K + kb + c8 * 8);
                if (SPLIT == 3)
                    cpa16(base + ASZ + r * 80 + c8 * 16,
                          pAl + (size_t)(m0 + r) * K + kb + c8 * 8);
            }
        }
#pragma unroll
        for (int j = 0; j < (BN == 128 ? 2 : 1); j++) {
            int u = tid + j * 256, r = u >> 2, c8 = u & 3;
            cpa16(base + OFF_BH + r * 80 + c8 * 16,
                  pBh + (size_t)(n0 + r) * K + kb + c8 * 8);
            if (SPLIT == 3)
                cpa16(base + OFF_BH + BSZ + r * 80 + c8 * 16,
                      pBl + (size_t)(n0 + r) * K + kb + c8 * 8);
        }
    };

    // ----- MODE 4: p_t fp16 loads + scale + att write + fp16 smem store -----
    uint2 rAp[4];
    auto loadA = [&](int c) {
        const int kb = c * BK;
#pragma unroll
        for (int j = 0; j < 4; j++) {
            int u = tid + j * 256, r = u >> 3, c4 = u & 7;
            rAp[j] = *(const uint2*)(pPt + (size_t)(m0 + r) * K + kb + c4 * 4);
        }
    };
    auto storeA = [&](int c) {
        const int st = c % NSTG, kb = c * BK;
        char* base = smem + st * STG;
        const int t = c >> 2;                  // 128-wide k-tile index
        if (t != cur_t) {
            cur_t = t;
#pragma unroll
            for (int j = 0; j < 4; j++) {
                const int r = (tid >> 3) + j * 32;
                const float Mt = stats[((size_t)z * 16 + t) * SQ + m0 + r].x;
                sc[j] = __expf(Mt - rs[j].x) * rs[j].y;
            }
        }
#pragma unroll
        for (int j = 0; j < 4; j++) {
            int u = tid + j * 256, r = u >> 3, c4 = u & 7;
            __half2 h01 = *(__half2*)&rAp[j].x;
            __half2 h23 = *(__half2*)&rAp[j].y;
            float4 p;
            p.x = __low2float(h01)  * sc[j];
            p.y = __high2float(h01) * sc[j];
            p.z = __low2float(h23)  * sc[j];
            p.w = __high2float(h23) * sc[j];
            *(float4*)(pW + (size_t)(m0 + r) * K + kb + c4 * 4) = p;
            __half2 o0 = __floats2half2_rn(p.x, p.y);
            __half2 o1 = __floats2half2_rn(p.z, p.w);
            *(int2*)(base + r * 80 + c4 * 8) = make_int2(*(int*)&o0, *(int*)&o1);
        }
    };

    float acc[2][NT][4];
#pragma unroll
    for (int a = 0; a < 2; a++)
#pragma unroll
        for (int b = 0; b < NT; b++)
#pragma unroll
            for (int c = 0; c < 4; c++) acc[a][b][c] = 0.0f;

    // prologue: issue chunks 0..NSTG-2
#pragma unroll
    for (int s = 0; s < NSTG - 1; s++) {
        if (s < NCH) issue(s, s);
        cpa_commit();
    }
    if (ACONV) { loadA(0); storeA(0); }

    for (int c = 0; c < NCH; c++) {
        const int st = c % NSTG;
        cpa_waitg<NSTG - 2>();
        __syncthreads();
        if (c + NSTG - 1 < NCH) issue(c + NSTG - 1, (c + NSTG - 1) % NSTG);
        cpa_commit();
        if (ACONV && c + 1 < NCH) loadA(c + 1);

        const uint32_t aBase = sb + st * STG;
        const uint32_t bBase = aBase + OFF_BH;
#pragma unroll
        for (int ks = 0; ks < 2; ks++) {
            uint32_t ah[2][4], al[2][4];
#pragma unroll
            for (int mt = 0; mt < 2; mt++) {
                uint32_t ad = aBase + (wm * 32 + mt * 16 + (lane & 15)) * 80
                              + ks * 32 + ((lane >> 4) << 4);
                ldm4(ah[mt], ad);
                if (SPLIT == 3) ldm4(al[mt], ad + ASZ);
            }
            const int g = lane >> 3;
            const int nsub = (g >> 1) * 8, khalf = (g & 1) * 16;
#pragma unroll
            for (int ntp = 0; ntp < NT / 2; ntp++) {
                uint32_t bd = bBase
                    + (wn * NSPAN + ntp * 16 + nsub + (lane & 7)) * 80
                    + ks * 32 + khalf;
                uint32_t bh[4];
                ldm4(bh, bd);
#pragma unroll
                for (int mt = 0; mt < 2; mt++) {
                    mma16816<BF16>(acc[mt][2 * ntp],     ah[mt], bh[0], bh[1]);
                    mma16816<BF16>(acc[mt][2 * ntp + 1], ah[mt], bh[2], bh[3]);
                }
                if (SPLIT == 3) {
                    uint32_t bl[4];
                    ldm4(bl, bd + BSZ);
#pragma unroll
                    for (int mt = 0; mt < 2; mt++) {
                        mma16816<BF16>(acc[mt][2 * ntp],     ah[mt], bl[0], bl[1]);
                        mma16816<BF16>(acc[mt][2 * ntp + 1], ah[mt], bl[2], bl[3]);
                        mma16816<BF16>(acc[mt][2 * ntp],     al[mt], bh[0], bh[1]);
                        mma16816<BF16>(acc[mt][2 * ntp + 1], al[mt], bh[2], bh[3]);
                    }
                }
            }
        }
        if (ACONV && c + 1 < NCH) storeA(c + 1);
    }
    __syncthreads();                               // protect smem reuse in epilogue

    // ---------------- epilogue ----------------
    float (*sf)[129] = (float(*)[129])smem;        // MODE5-V staging

#pragma unroll
    for (int mt = 0; mt < 2; mt++)
#pragma unroll
        for (int nt = 0; nt < NT; nt++)
#pragma unroll
            for (int hh = 0; hh < 2; hh++) {
                float v0 = acc[mt][nt][hh * 2 + 0];
                float v1 = acc[mt][nt][hh * 2 + 1];
                const int m_loc = wm * 32 + mt * 16 + (lane >> 2) + hh * 8;
                const int n_loc = wn * NSPAN + nt * 8 + (lane & 3) * 2;
                const int gm = m0 + m_loc, gn = n0 + n_loc;

                if (MODE == 2) {
                    v0 += bias[gn]; v1 += bias[gn + 1];
                    *(float2*)&outf[(size_t)gm * DM + gn] = make_float2(v0, v1);
                } else if (MODE == 3) {
                    v0 *= 0.125f; v1 *= 0.125f;
                    const size_t midx = ((size_t)(z >> 4) * SQ + gm) * SQ + gn;
                    int2 mv = *(const int2*)(mask + midx);
                    if (mv.x == 0) v0 = 1e-9f;
                    if (mv.y == 0) v1 = 1e-9f;
                    acc[mt][nt][hh * 2 + 0] = v0;   // keep for stats/p_t pass
                    acc[mt][nt][hh * 2 + 1] = v1;
                } else if (MODE == 4) {
                    const int b = z >> 4, h = z & 15;
                    const size_t a = (((size_t)(b * SQ + gm)) * DM + h * DKH + gn) >> 1;
                    ohi[a] = pack_bf2(v0, v1);
                    olo[a] = pack_bf2(v0 - __bfloat162float(__float2bfloat16(v0)),
                                      v1 - __bfloat162float(__float2bfloat16(v1)));
                } else if (MODE == 5) {
                    v0 += bias[gn]; v1 += bias[gn + 1];
                    if (sec < 2) {
                        const int gnl = gn & 1023;
                        const int b = gm >> 11, s = gm & 2047, h = gnl >> 6, d = gnl & 63;
                        const size_t a = ((((size_t)(b * NH + h)) * SQ + s) * DKH + d) >> 1;
                        (sec ? olo : ohi)[a] = pack_hf2(v0, v1);
                    } else {
                        sf[m_loc][n_loc]     = v0;
                        sf[m_loc][n_loc + 1] = v1;
                    }
                }
            }

    if (MODE == 5 && sec == 2) {                   // V transpose -> [bh, d, s]
        __syncthreads();
        const int b = m0 >> 11, s0 = m0 & 2047;
        const int gnl_base = n0 & 1023;
#pragma unroll
        for (int it = 0; it < 16; it++) {
            const int rn = it * 8 + wid;
            const int gnl = gnl_base + rn;
            const int h = gnl >> 6, d = gnl & 63;
            uint32_t* orow = ov + ((((size_t)(b * NH + h)) * DKH + d) * SQ + s0) / 2;
#pragma unroll
            for (int j = 0; j < 2; j++) {
                const int sp = j * 64 + 2 * lane;
                orow[j * 32 + lane] = pack_hf2(sf[sp][rn], sf[sp + 1][rn]);
            }
        }
    }

    if (MODE == 3) {
        float* smax = (float*)smem;                // [2][128]
        float* ssum = smax + 256;
        // phase 1: per-half row max
#pragma unroll
        for (int mt = 0; mt < 2; mt++)
#pragma unroll
            for (int hh = 0; hh < 2; hh++) {
                float mx = -1e30f;
#pragma unroll
                for (int nt = 0; nt < NT; nt++)
                    mx = fmaxf(mx, fmaxf(acc[mt][nt][hh * 2], acc[mt][nt][hh * 2 + 1]));
                mx = fmaxf(mx, __shfl_xor_sync(0xffffffffu, mx, 1));
                mx = fmaxf(mx, __shfl_xor_sync(0xffffffffu, mx, 2));
                if ((lane & 3) == 0)
                    smax[wn * 128 + wm * 32 + mt * 16 + hh * 8 + (lane >> 2)] = mx;
            }
        __syncthreads();
        // phase 2: combined max -> p_t writes + sums
#pragma unroll
        for (int mt = 0; mt < 2; mt++)
#pragma unroll
            for (int hh = 0; hh < 2; hh++) {
                const int m_loc = wm * 32 + mt * 16 + hh * 8 + (lane >> 2);
                const float mx = fmaxf(smax[m_loc], smax[128 + m_loc]);
                const int gm = m0 + m_loc;
                float sm = 0.0f;
#pragma unroll
                for (int nt = 0; nt < NT; nt++) {
                    const float e0 = __expf(acc[mt][nt][hh * 2 + 0] - mx);
                    const float e1 = __expf(acc[mt][nt][hh * 2 + 1] - mx);
                    sm += e0 + e1;
                    const int gn = n0 + wn * NSPAN + nt * 8 + (lane & 3) * 2;
                    ohi[(((size_t)z * SQ + gm) * SQ + gn) >> 1] = pack_hf2(e0, e1);
                }
                sm += __shfl_xor_sync(0xffffffffu, sm, 1);
                sm += __shfl_xor_sync(0xffffffffu, sm, 2);
                if ((lane & 3) == 0) ssum[wn * 128 + m_loc] = sm;
            }
        __syncthreads();
        if (tid < 128) {
            stats[((size_t)z * 16 + blockIdx.x) * SQ + m0 + tid] =
                make_float2(fmaxf(smax[tid], smax[128 + tid]),
                            ssum[tid] + ssum[128 + tid]);
        }
    }
}

// ---------------- combine per-tile stats -> per-row (max, 1/sum) ----------------
__global__ __launch_bounds__(256)
void stats_reduce(const float2* __restrict__ stats, float2* __restrict__ rowstat)
{
    const int idx = blockIdx.x * 256 + threadIdx.x;    // 65536 rows
    const int bh = idx >> 11, q = idx & 2047;
    float2 t[16];
    float M = -1e30f;
#pragma unroll
    for (int kb = 0; kb < 16; kb++) {
        t[kb] = stats[((size_t)bh * 16 + kb) * SQ + q];
        M = fmaxf(M, t[kb].x);
    }
    float S = 0.0f;
#pragma unroll
    for (int kb = 0; kb < 16; kb++) S += t[kb].y * __expf(t[kb].x - M);
    rowstat[idx] = make_float2(M, 1.0f / S);
}

// ---------------- fp32 -> fp16 ----------------
__global__ __launch_bounds__(256)
void cvt_half(const float* __restrict__ x, __half* __restrict__ o, size_t n4)
{
    size_t i = (size_t)blockIdx.x * blockDim.x + threadIdx.x;
    if (i >= n4) return;
    float4 v = ((const float4*)x)[i];
    __half2 h0 = __floats2half2_rn(v.x, v.y);
    __half2 h1 = __floats2half2_rn(v.z, v.w);
    ((int2*)o)[i] = make_int2(*(int*)&h0, *(int*)&h1);
}

// ---------------- fp32 -> bf16 hi/lo split (Wo only) ----------------
__global__ __launch_bounds__(256)
void cvt_split(const float* __restrict__ x, __nv_bfloat16* __restrict__ hi,
               __nv_bfloat16* __restrict__ lo, size_t n4)
{
    size_t i = (size_t)blockIdx.x * blockDim.x + threadIdx.x;
    if (i >= n4) return;
    float4 v = ((const float4*)x)[i];
    float f[4] = {v.x, v.y, v.z, v.w};
    uint32_t h[4], l[4];
#pragma unroll
    for (int j = 0; j < 4; j++) {
        __nv_bfloat16 hb = __float2bfloat16(f[j]);
        h[j] = (uint32_t)__bfloat16_as_ushort(hb);
        l[j] = (uint32_t)__bfloat16_as_ushort(__float2bfloat16(f[j] - __bfloat162float(hb)));
    }
    ((int2*)hi)[i] = make_int2((int)(h[0] | (h[1] << 16)), (int)(h[2] | (h[3] << 16)));
    ((int2*)lo)[i] = make_int2((int)(l[0] | (l[1] << 16)), (int)(l[2] | (l[3] << 16)));
}

// ---------------- concat bias ----------------
__global__ void concat_bias(const float* a, const float* b, const float* c, float* o)
{
    const int i = blockIdx.x * 256 + threadIdx.x;   // 3072
    o[i] = (i < 1024) ? a[i] : (i < 2048) ? b[i - 1024] : c[i - 2048];
}

// ============================================================
extern "C" void kernel_launch(void* const* d_in, const int* in_sizes, int n_in,
                              void* d_out, int out_size)
{
    const float* q    = (const float*)d_in[0];
    const float* k    = (const float*)d_in[1];
    const float* v    = (const float*)d_in[2];
    const int*   mask = (const int*)  d_in[3];
    const float* Wq   = (const float*)d_in[4];
    const float* bq   = (const float*)d_in[5];
    const float* Wk   = (const float*)d_in[6];
    const float* bk   = (const float*)d_in[7];
    const float* Wv   = (const float*)d_in[8];
    const float* bv   = (const float*)d_in[9];
    const float* Wo   = (const float*)d_in[10];
    const float* bo   = (const float*)d_in[11];

    __half *xq, *xk, *xv, *wqkv, *qh, *kh, *vt, *pt;
    float *bqkv;
    __nv_bfloat16 *wo_hi, *wo_lo, *cx_hi, *cx_lo;
    float *attscr, *dummy;
    float2 *statsp, *rowstatp;
    cudaGetSymbolAddress((void**)&xq, g_xq); cudaGetSymbolAddress((void**)&xk, g_xk);
    cudaGetSymbolAddress((void**)&xv, g_xv);
    cudaGetSymbolAddress((void**)&wqkv, g_wqkv);
    cudaGetSymbolAddress((void**)&bqkv, g_bqkv);
    cudaGetSymbolAddress((void**)&wo_hi, g_wo_hi); cudaGetSymbolAddress((void**)&wo_lo, g_wo_lo);
    cudaGetSymbolAddress((void**)&qh, g_qh); cudaGetSymbolAddress((void**)&kh, g_kh);
    cudaGetSymbolAddress((void**)&vt, g_vt);
    cudaGetSymbolAddress((void**)&pt, g_pt);
    cudaGetSymbolAddress((void**)&cx_hi, g_ctx_hi); cudaGetSymbolAddress((void**)&cx_lo, g_ctx_lo);
    cudaGetSymbolAddress((void**)&attscr, g_att_scratch);
    cudaGetSymbolAddress((void**)&dummy,  g_dummy_out);
    cudaGetSymbolAddress((void**)&statsp, g_stats);
    cudaGetSymbolAddress((void**)&rowstatp, g_rowstat);

    const long OUT_ELEMS = (long)NB * SQ * DM;
    const long ATT_ELEMS = (long)AN;
    float* outp = (float*)d_out;
    float* attp;
    if ((long)out_size >= OUT_ELEMS + ATT_ELEMS)      attp = outp + OUT_ELEMS;
    else if ((long)out_size == ATT_ELEMS) { attp = outp; outp = dummy; }
    else                                               attp = attscr;

    constexpr int SM_P1_128 = 3 * (10240 + 10240);          // 61440 (split1, 3-stage)
    constexpr int SM_PROJ   = 66048;                         // max(61440, 128*129*4)
    constexpr int SM_PV     = 3 * (10240 + 5120);            // 46080
    constexpr int SM_S3_128 = 2 * ((10240 + 10240) * 2);     // 81920 (split3, 2-stage)

    cudaFuncSetAttribute(mma_gemm<128, 5, 1, 0, 3, __half>,
                         cudaFuncAttributeMaxDynamicSharedMemorySize, SM_PROJ);
    cudaFuncSetAttribute(mma_gemm<128, 3, 1, 0, 3, __half>,
                         cudaFuncAttributeMaxDynamicSharedMemorySize, SM_P1_128);
    cudaFuncSetAttribute(mma_gemm<64, 4, 1, 1, 3, __half>,
                         cudaFuncAttributeMaxDynamicSharedMemorySize, SM_PV);
    cudaFuncSetAttribute(mma_gemm<128, 2, 3, 0, 2, __nv_bfloat16>,
                         cudaFuncAttributeMaxDynamicSharedMemorySize, SM_S3_128);

    // conversions
    cvt_half<<<(int)(XN / 4 / 256), 256>>>(q, xq, XN / 4);
    cvt_half<<<(int)(XN / 4 / 256), 256>>>(k, xk, XN / 4);
    cvt_half<<<(int)(XN / 4 / 256), 256>>>(v, xv, XN / 4);
    cvt_half<<<(int)(WN / 4 / 256), 256>>>(Wq, wqkv,          WN / 4);
    cvt_half<<<(int)(WN / 4 / 256), 256>>>(Wk, wqkv + WN,     WN / 4);
    cvt_half<<<(int)(WN / 4 / 256), 256>>>(Wv, wqkv + 2 * WN, WN / 4);
    cvt_split<<<(int)(WN / 4 / 256), 256>>>(Wo, wo_hi, wo_lo, WN / 4);
    concat_bias<<<12, 256>>>(bq, bk, bv, bqkv);

    // merged QKV projection (M=4096, N=3072, K=1024)
    mma_gemm<128, 5, 1, 0, 3, __half><<<dim3(24, 32, 1), 256, SM_PROJ>>>(
        xq, nullptr, nullptr, wqkv, nullptr, bqkv, nullptr, nullptr,
        (uint32_t*)qh, (uint32_t*)kh, (uint32_t*)vt, nullptr, nullptr,
        xk, xv, DM, 0, 0);

    // scores: p_t fp16 + per-tile row stats
    mma_gemm<128, 3, 1, 0, 3, __half><<<dim3(16, 16, NBH), 256, SM_P1_128>>>(
        qh, nullptr, nullptr, kh, nullptr, nullptr, mask, nullptr,
        (uint32_t*)pt, nullptr, nullptr, statsp, nullptr,
        nullptr, nullptr, DKH, (size_t)SQ * DKH, (size_t)SQ * DKH);

    stats_reduce<<<NBH * SQ / 256, 256>>>(statsp, rowstatp);

    // normalize + PV: reads p_t, writes att fp32 + ctx hi/lo
    mma_gemm<64, 4, 1, 1, 3, __half><<<dim3(1, 16, NBH), 256, SM_PV>>>(
        nullptr, nullptr, pt, vt, nullptr, nullptr, nullptr, attp,
        (uint32_t*)cx_hi, (uint32_t*)cx_lo, nullptr, statsp, rowstatp,
        nullptr, nullptr, SQ, (size_t)SQ * SQ, (size_t)DKH * SQ);

    // output projection (split-3 bf16)
    mma_gemm<128, 2, 3, 0, 2, __nv_bfloat16><<<dim3(8, 32, 1), 256, SM_S3_128>>>(
        cx_hi, cx_lo, nullptr, wo_hi, wo_lo, bo, nullptr, outp,
        nullptr, nullptr, nullptr, nullptr, nullptr,
        nullptr, nullptr, DM, 0, 0);
}